// round 11
// baseline (speedup 1.0000x reference)
#include <cuda_runtime.h>
#include <cuda_fp16.h>
#include <math.h>
#include <cstdint>

// Problem constants
#define T_SEQ 4096
#define D_MODEL 2048
#define N_HEADS 16
#define N_KV 4
#define DH 128
#define HALF 64
#define KV_DIM 512   // N_KV * DH

// Scratch (device globals; no allocation allowed)
__device__ __half g_qh[T_SEQ * D_MODEL];
__device__ __half g_kh[T_SEQ * KV_DIM];
__device__ __half g_vh[T_SEQ * KV_DIM];
__device__ float  g_y[T_SEQ * D_MODEL];

// ---------------------------------------------------------------------------
// helpers
// ---------------------------------------------------------------------------
__device__ __forceinline__ uint32_t pack2h(float lo, float hi) {
    __half2 h = __floats2half2_rn(lo, hi);   // .x = lo -> low 16 bits
    return *(uint32_t*)&h;
}

__device__ __forceinline__ void mma_f16(float* d, const uint32_t* a,
                                        const uint32_t* b, const float* c) {
    asm volatile(
        "mma.sync.aligned.m16n8k16.row.col.f32.f16.f16.f32 "
        "{%0,%1,%2,%3}, {%4,%5,%6,%7}, {%8,%9}, {%10,%11,%12,%13};"
        : "=f"(d[0]), "=f"(d[1]), "=f"(d[2]), "=f"(d[3])
        : "r"(a[0]), "r"(a[1]), "r"(a[2]), "r"(a[3]),
          "r"(b[0]), "r"(b[1]),
          "f"(c[0]), "f"(c[1]), "f"(c[2]), "f"(c[3]));
}

__device__ __forceinline__ uint32_t smem_u32(const void* p) {
    uint32_t a;
    asm("{ .reg .u64 t; cvta.to.shared.u64 t, %1; cvt.u32.u64 %0, t; }" : "=r"(a) : "l"(p));
    return a;
}

__device__ __forceinline__ void ldmx4(uint32_t& r0, uint32_t& r1,
                                      uint32_t& r2, uint32_t& r3, uint32_t addr) {
    asm volatile("ldmatrix.sync.aligned.m8n8.x4.shared.b16 {%0,%1,%2,%3}, [%4];"
                 : "=r"(r0), "=r"(r1), "=r"(r2), "=r"(r3) : "r"(addr));
}

__device__ __forceinline__ void ldmx4t(uint32_t& b0, uint32_t& b1,
                                       uint32_t& b2, uint32_t& b3, uint32_t addr) {
    asm volatile("ldmatrix.sync.aligned.m8n8.x4.trans.shared.b16 {%0,%1,%2,%3}, [%4];"
                 : "=r"(b0), "=r"(b1), "=r"(b2), "=r"(b3) : "r"(addr));
}

// ---------------------------------------------------------------------------
// FP16 tensor-core GEMM, software-pipelined, ldmatrix fragment loads.
// C[M,N] = A[M,K] @ B[K,N]; A,B fp32 in; C fp32 or fp16 out (template).
// CTA 128x128, BK=16, 256 threads = 8 warps (4m x 2n), warp tile 32x64.
// ---------------------------------------------------------------------------
template <typename TOut>
__global__ __launch_bounds__(256, 2)
void sgemm_f16(const float* __restrict__ A, const float* __restrict__ B,
               TOut* __restrict__ C, int M, int N, int K) {
    __shared__ uint32_t As[2][128][12];   // [buf][m][k2] packed half2 k-pairs
    __shared__ uint32_t Bs[2][128][12];   // [buf][n][k2]  (B transposed)

    const int tid = threadIdx.x;
    const int wid = tid >> 5;
    const int lane = tid & 31;
    const int g = lane >> 2;
    const int t = lane & 3;
    const int m0 = blockIdx.y * 128;
    const int n0 = blockIdx.x * 128;
    const int wm = (wid & 3) * 32;
    const int wn = (wid >> 2) * 64;

    // staging indices
    const int aRow = tid >> 2;
    const int aK4  = (tid & 3) << 2;
    const int aK2  = (tid & 3) << 1;
    const int bN   = tid & 127;
    const int bKh  = tid >> 7;

    // ldmatrix source addresses (fixed per thread, per buffer)
    uint32_t aAddr[2][2], bAddr[2][4];
#pragma unroll
    for (int buf = 0; buf < 2; ++buf) {
#pragma unroll
        for (int mt = 0; mt < 2; ++mt)
            aAddr[buf][mt] = smem_u32(&As[buf][wm + mt * 16 + (lane & 15)][0]) +
                             ((lane >> 4) << 4);
#pragma unroll
        for (int p = 0; p < 4; ++p)
            bAddr[buf][p] = smem_u32(&Bs[buf][wn + p * 16 + (lane & 7) + ((lane >> 4) << 3)][0]) +
                            (((lane >> 3) & 1) << 4);
    }

    float acc[2][8][4];
#pragma unroll
    for (int mt = 0; mt < 2; ++mt)
#pragma unroll
        for (int nt = 0; nt < 8; ++nt)
#pragma unroll
            for (int r = 0; r < 4; ++r) acc[mt][nt][r] = 0.f;

    float4 ar[2];
    float  bv[4][2];

    // ---- prologue: load + stage tile 0
#pragma unroll
    for (int l = 0; l < 2; ++l)
        ar[l] = *(const float4*)(A + (size_t)(m0 + aRow + l * 64) * K + aK4);
#pragma unroll
    for (int l = 0; l < 4; ++l) {
        int k2 = bKh + 2 * l;
        bv[l][0] = B[(size_t)(2 * k2) * N + n0 + bN];
        bv[l][1] = B[(size_t)(2 * k2 + 1) * N + n0 + bN];
    }
#pragma unroll
    for (int l = 0; l < 2; ++l)
        *(uint2*)(&As[0][aRow + l * 64][aK2]) =
            make_uint2(pack2h(ar[l].x, ar[l].y), pack2h(ar[l].z, ar[l].w));
#pragma unroll
    for (int l = 0; l < 4; ++l)
        Bs[0][bN][bKh + 2 * l] = pack2h(bv[l][0], bv[l][1]);
    __syncthreads();

    const int KT = K >> 4;
    for (int kt = 0; kt < KT; ++kt) {
        const int buf = kt & 1;

        // ---- prefetch tile kt+1
        if (kt + 1 < KT) {
            const int k0n = (kt + 1) << 4;
#pragma unroll
            for (int l = 0; l < 2; ++l)
                ar[l] = *(const float4*)(A + (size_t)(m0 + aRow + l * 64) * K + k0n + aK4);
#pragma unroll
            for (int l = 0; l < 4; ++l) {
                int k2 = bKh + 2 * l;
                bv[l][0] = B[(size_t)(k0n + 2 * k2) * N + n0 + bN];
                bv[l][1] = B[(size_t)(k0n + 2 * k2 + 1) * N + n0 + bN];
            }
        }

        // ---- fragments via ldmatrix
        uint32_t af[2][4], bf[4][4];
#pragma unroll
        for (int mt = 0; mt < 2; ++mt)
            ldmx4(af[mt][0], af[mt][1], af[mt][2], af[mt][3], aAddr[buf][mt]);
#pragma unroll
        for (int p = 0; p < 4; ++p)
            ldmx4(bf[p][0], bf[p][1], bf[p][2], bf[p][3], bAddr[buf][p]);

#pragma unroll
        for (int nt = 0; nt < 8; ++nt) {
            uint32_t b[2] = {bf[nt >> 1][(nt & 1) << 1], bf[nt >> 1][((nt & 1) << 1) + 1]};
#pragma unroll
            for (int mt = 0; mt < 2; ++mt)
                mma_f16(acc[mt][nt], af[mt], b, acc[mt][nt]);
        }

        // ---- stage tile kt+1
        if (kt + 1 < KT) {
            const int nb = buf ^ 1;
#pragma unroll
            for (int l = 0; l < 2; ++l)
                *(uint2*)(&As[nb][aRow + l * 64][aK2]) =
                    make_uint2(pack2h(ar[l].x, ar[l].y), pack2h(ar[l].z, ar[l].w));
#pragma unroll
            for (int l = 0; l < 4; ++l)
                Bs[nb][bN][bKh + 2 * l] = pack2h(bv[l][0], bv[l][1]);
            __syncthreads();
        }
    }

    // ---- epilogue (fp32 or fp16 output)
#pragma unroll
    for (int mt = 0; mt < 2; ++mt) {
        const int r0 = m0 + wm + mt * 16;
#pragma unroll
        for (int nt = 0; nt < 8; ++nt) {
            const int c0 = n0 + wn + nt * 8 + t * 2;
            if (sizeof(TOut) == 4) {
                float* Cf = (float*)C;
                *(float2*)(Cf + (size_t)(r0 + g) * N + c0) =
                    make_float2(acc[mt][nt][0], acc[mt][nt][1]);
                *(float2*)(Cf + (size_t)(r0 + g + 8) * N + c0) =
                    make_float2(acc[mt][nt][2], acc[mt][nt][3]);
            } else {
                __half* Ch = (__half*)C;
                *(uint32_t*)(Ch + (size_t)(r0 + g) * N + c0) =
                    pack2h(acc[mt][nt][0], acc[mt][nt][1]);
                *(uint32_t*)(Ch + (size_t)(r0 + g + 8) * N + c0) =
                    pack2h(acc[mt][nt][2], acc[mt][nt][3]);
            }
        }
    }
}

// ---------------------------------------------------------------------------
// RoPE in-place on fp16 [T, nheads, 128] buffers (rowstride in halves).
// Each thread handles 2 adjacent rotation indices via half2.
// ---------------------------------------------------------------------------
__global__ void rope_kernel_h(__half* __restrict__ buf, int nheads, int rowstride) {
    int idx = blockIdx.x * blockDim.x + threadIdx.x;
    int total = T_SEQ * nheads * 32;        // 32 half2 pairs per (t,h)
    if (idx >= total) return;
    int i2 = idx & 31;                      // pair index: elements 2*i2, 2*i2+1
    int h = (idx >> 5) % nheads;
    int t = idx / (32 * nheads);

    float i0 = (float)(2 * i2);
    float i1 = (float)(2 * i2 + 1);
    float inv0 = powf(10000.f, -i0 / (float)HALF);
    float inv1 = powf(10000.f, -i1 / (float)HALF);
    float s0, c0, s1, c1;
    sincosf((float)t * inv0, &s0, &c0);
    sincosf((float)t * inv1, &s1, &c1);

    __half* base = buf + (size_t)t * rowstride + h * DH;
    float2 x1 = __half22float2(*(__half2*)(base + 2 * i2));
    float2 x2 = __half22float2(*(__half2*)(base + HALF + 2 * i2));
    *(__half2*)(base + 2 * i2) =
        __floats2half2_rn(x1.x * c0 - x2.x * s0, x1.y * c1 - x2.y * s1);
    *(__half2*)(base + HALF + 2 * i2) =
        __floats2half2_rn(x1.x * s0 + x2.x * c0, x1.y * s1 + x2.y * c1);
}

// ---------------------------------------------------------------------------
// Flash attention v5 (all fp16 mma, fp16 inputs — staging is a pure copy).
// CTA = 64 queries x 1 head, 128 threads / 4 warps, warp = 16 q rows x d=128.
// Smem (u32): Qh[64][68] half-pairs, Kh[64][68], Vh fp16 [64][136].
// ---------------------------------------------------------------------------
#define AOQ 0
#define AOK 4352
#define AOV 8704
#define ATTN_SMEM_BYTES ((8704 + 4352) * 4)   // 52224

__global__ __launch_bounds__(128)
void attn_kernel(const __half* __restrict__ q, const __half* __restrict__ k,
                 const __half* __restrict__ v, float* __restrict__ y) {
    extern __shared__ uint32_t smu[];
    uint32_t* Qh = smu + AOQ;              // [64][68] half2 pairs along d
    uint32_t* Kh = smu + AOK;              // [64][68]
    __half*   Vh = (__half*)(smu + AOV);   // [64][136] row-major [key][d]

    const int qb = blockIdx.x;
    const int hq = blockIdx.y;
    const int hkv = hq >> 2;
    const int q0 = qb * 64;
    const int tid = threadIdx.x;
    const int wid = tid >> 5;
    const int lane = tid & 31;
    const int g = lane >> 2;
    const int t = lane & 3;
    const int r0 = wid * 16;               // warp's q-row group
    const int rg0 = q0 + r0 + g;
    const int rg1 = rg0 + 8;

    // ---- stage Q once (pure uint4 copy: 64 rows x 16 uint4)
#pragma unroll
    for (int l = 0; l < 8; ++l) {
        int lin = tid + l * 128;
        int row = lin >> 4;
        int d8 = lin & 15;
        uint4 u = *(const uint4*)(q + (size_t)(q0 + row) * D_MODEL + hq * DH + d8 * 8);
        *(uint4*)(Qh + row * 68 + d8 * 4) = u;
    }

    float acc[16][4];                      // O: rows {g,g+8} x d cols
#pragma unroll
    for (int n = 0; n < 16; ++n)
#pragma unroll
        for (int r = 0; r < 4; ++r) acc[n][r] = 0.f;
    float m_i[2] = {-1e30f, -1e30f};
    float l_i[2] = {0.f, 0.f};

    const float scale = 0.08838834764831845f;   // 1/sqrt(128)

    for (int jb = 0; jb <= qb; ++jb) {
        const int j0 = jb * 64;
        __syncthreads();   // previous tile fully consumed

        // ---- stage K + V (pure uint4 copies)
#pragma unroll
        for (int l = 0; l < 8; ++l) {
            int lin = tid + l * 128;
            int row = lin >> 4;
            int d8 = lin & 15;
            uint4 ku = *(const uint4*)(k + (size_t)(j0 + row) * KV_DIM + hkv * DH + d8 * 8);
            *(uint4*)(Kh + row * 68 + d8 * 4) = ku;
            uint4 vu = *(const uint4*)(v + (size_t)(j0 + row) * KV_DIM + hkv * DH + d8 * 8);
            *(uint4*)(Vh + row * 136 + d8 * 8) = vu;
        }
        __syncthreads();

        if (j0 > q0 + r0 + 15) continue;   // warp fully above this key block

        // ---- S = Q K^T : 8 n-tiles (64 keys), 8 k16 steps (d=128)
        float sf[8][4];
#pragma unroll
        for (int nt = 0; nt < 8; ++nt)
#pragma unroll
            for (int r = 0; r < 4; ++r) sf[nt][r] = 0.f;

        const uint32_t* qr0 = Qh + (r0 + g) * 68;
        const uint32_t* qr1 = Qh + (r0 + g + 8) * 68;
#pragma unroll
        for (int ks = 0; ks < 8; ++ks) {
            const int kk = ks * 8;
            uint32_t a[4] = {qr0[kk + t], qr1[kk + t], qr0[kk + 4 + t], qr1[kk + 4 + t]};
#pragma unroll
            for (int nt = 0; nt < 8; ++nt) {
                const uint32_t* kr = Kh + (nt * 8 + g) * 68 + kk;
                uint32_t b[2] = {kr[t], kr[4 + t]};
                mma_f16(sf[nt], a, b, sf[nt]);
            }
        }

        // ---- scale + causal mask (diagonal band only)
#pragma unroll
        for (int nt = 0; nt < 8; ++nt) {
            sf[nt][0] *= scale; sf[nt][1] *= scale;
            sf[nt][2] *= scale; sf[nt][3] *= scale;
        }
        if (j0 + 63 > rg0) {
#pragma unroll
            for (int nt = 0; nt < 8; ++nt) {
                const int c = j0 + nt * 8 + 2 * t;
                if (c     > rg0) sf[nt][0] = -1e30f;
                if (c + 1 > rg0) sf[nt][1] = -1e30f;
                if (c     > rg1) sf[nt][2] = -1e30f;
                if (c + 1 > rg1) sf[nt][3] = -1e30f;
            }
        }

        // ---- online softmax (quad-local)
        float mx0 = -1e30f, mx1 = -1e30f;
#pragma unroll
        for (int nt = 0; nt < 8; ++nt) {
            mx0 = fmaxf(mx0, fmaxf(sf[nt][0], sf[nt][1]));
            mx1 = fmaxf(mx1, fmaxf(sf[nt][2], sf[nt][3]));
        }
        mx0 = fmaxf(mx0, __shfl_xor_sync(0xffffffffu, mx0, 1));
        mx0 = fmaxf(mx0, __shfl_xor_sync(0xffffffffu, mx0, 2));
        mx1 = fmaxf(mx1, __shfl_xor_sync(0xffffffffu, mx1, 1));
        mx1 = fmaxf(mx1, __shfl_xor_sync(0xffffffffu, mx1, 2));

        const float mn0 = fmaxf(m_i[0], mx0);
        const float mn1 = fmaxf(m_i[1], mx1);
        const float al0 = __expf(m_i[0] - mn0);
        const float al1 = __expf(m_i[1] - mn1);

        float sum0 = 0.f, sum1 = 0.f;
#pragma unroll
        for (int nt = 0; nt < 8; ++nt) {
            sf[nt][0] = __expf(sf[nt][0] - mn0);
            sf[nt][1] = __expf(sf[nt][1] - mn0);
            sf[nt][2] = __expf(sf[nt][2] - mn1);
            sf[nt][3] = __expf(sf[nt][3] - mn1);
            sum0 += sf[nt][0] + sf[nt][1];
            sum1 += sf[nt][2] + sf[nt][3];
        }
        sum0 += __shfl_xor_sync(0xffffffffu, sum0, 1);
        sum0 += __shfl_xor_sync(0xffffffffu, sum0, 2);
        sum1 += __shfl_xor_sync(0xffffffffu, sum1, 1);
        sum1 += __shfl_xor_sync(0xffffffffu, sum1, 2);

        l_i[0] = l_i[0] * al0 + sum0;
        l_i[1] = l_i[1] * al1 + sum1;
        m_i[0] = mn0;
        m_i[1] = mn1;

#pragma unroll
        for (int n = 0; n < 16; ++n) {
            acc[n][0] *= al0; acc[n][1] *= al0;
            acc[n][2] *= al1; acc[n][3] *= al1;
        }

        // ---- O += P V : P packed from fragments, V via ldmatrix.x4.trans
        const int vrow = lane & 15;
        const int vcol8 = (lane >> 4) * 8;
#pragma unroll
        for (int ks = 0; ks < 4; ++ks) {
            uint32_t a[4] = {pack2h(sf[2 * ks][0],     sf[2 * ks][1]),
                             pack2h(sf[2 * ks][2],     sf[2 * ks][3]),
                             pack2h(sf[2 * ks + 1][0], sf[2 * ks + 1][1]),
                             pack2h(sf[2 * ks + 1][2], sf[2 * ks + 1][3])};
            const __half* vbase = Vh + (16 * ks + vrow) * 136 + vcol8;
#pragma unroll
            for (int ntp = 0; ntp < 8; ++ntp) {
                uint32_t b0, b1, b2, b3;
                ldmx4t(b0, b1, b2, b3, smem_u32(vbase + ntp * 16));
                uint32_t blo[2] = {b0, b1};
                uint32_t bhi[2] = {b2, b3};
                mma_f16(acc[2 * ntp],     a, blo, acc[2 * ntp]);
                mma_f16(acc[2 * ntp + 1], a, bhi, acc[2 * ntp + 1]);
            }
        }
    }

    // ---- normalize + write y rows rg0, rg1 (fp32)
    const float i0 = 1.f / l_i[0];
    const float i1 = 1.f / l_i[1];
    float* y0 = y + (size_t)rg0 * D_MODEL + hq * DH;
    float* y1 = y + (size_t)rg1 * D_MODEL + hq * DH;
#pragma unroll
    for (int n = 0; n < 16; ++n) {
        const int c0 = n * 8 + 2 * t;
        *(float2*)(y0 + c0) = make_float2(acc[n][0] * i0, acc[n][1] * i0);
        *(float2*)(y1 + c0) = make_float2(acc[n][2] * i1, acc[n][3] * i1);
    }
}

// ---------------------------------------------------------------------------
extern "C" void kernel_launch(void* const* d_in, const int* in_sizes, int n_in,
                              void* d_out, int out_size) {
    const float* x  = (const float*)d_in[0];
    const float* Wq = (const float*)d_in[1];
    const float* Wk = (const float*)d_in[2];
    const float* Wv = (const float*)d_in[3];
    const float* Wo = (const float*)d_in[4];
    float* out = (float*)d_out;

    void *pq, *pk, *pv, *py;
    cudaGetSymbolAddress(&pq, g_qh);
    cudaGetSymbolAddress(&pk, g_kh);
    cudaGetSymbolAddress(&pv, g_vh);
    cudaGetSymbolAddress(&py, g_y);
    __half* qh = (__half*)pq;
    __half* kh = (__half*)pk;
    __half* vh = (__half*)pv;
    float*  y  = (float*)py;

    // Projections (fp16 tensor cores, pipelined, fp16 outputs)
    sgemm_f16<__half><<<dim3(D_MODEL / 128, T_SEQ / 128), 256>>>(x, Wq, qh, T_SEQ, D_MODEL, D_MODEL);
    sgemm_f16<__half><<<dim3(KV_DIM / 128, T_SEQ / 128), 256>>>(x, Wk, kh, T_SEQ, KV_DIM, D_MODEL);
    sgemm_f16<__half><<<dim3(KV_DIM / 128, T_SEQ / 128), 256>>>(x, Wv, vh, T_SEQ, KV_DIM, D_MODEL);

    // RoPE on fp16 buffers
    {
        int nq = T_SEQ * N_HEADS * 32;
        rope_kernel_h<<<(nq + 255) / 256, 256>>>(qh, N_HEADS, D_MODEL);
        int nk = T_SEQ * N_KV * 32;
        rope_kernel_h<<<(nk + 255) / 256, 256>>>(kh, N_KV, KV_DIM);
    }

    // Attention (all-mma, fp16 inputs)
    cudaFuncSetAttribute(attn_kernel, cudaFuncAttributeMaxDynamicSharedMemorySize, ATTN_SMEM_BYTES);
    attn_kernel<<<dim3(T_SEQ / 64, N_HEADS), 128, ATTN_SMEM_BYTES>>>(qh, kh, vh, y);

    // Output projection (fp32 output)
    sgemm_f16<float><<<dim3(D_MODEL / 128, T_SEQ / 128), 256>>>(y, Wo, out, T_SEQ, D_MODEL, D_MODEL);
}

// round 12
// speedup vs baseline: 1.0840x; 1.0840x over previous
#include <cuda_runtime.h>
#include <cuda_fp16.h>
#include <math.h>
#include <cstdint>

// Problem constants
#define T_SEQ 4096
#define D_MODEL 2048
#define N_HEADS 16
#define N_KV 4
#define DH 128
#define HALF 64
#define KV_DIM 512   // N_KV * DH

// Scratch (device globals; no allocation allowed)
__device__ __half g_qh[T_SEQ * D_MODEL];
__device__ __half g_kh[T_SEQ * KV_DIM];
__device__ __half g_vh[T_SEQ * KV_DIM];
__device__ float  g_y[T_SEQ * D_MODEL];

// ---------------------------------------------------------------------------
// helpers
// ---------------------------------------------------------------------------
__device__ __forceinline__ uint32_t pack2h(float lo, float hi) {
    __half2 h = __floats2half2_rn(lo, hi);   // .x = lo -> low 16 bits
    return *(uint32_t*)&h;
}

__device__ __forceinline__ void mma_f16(float* d, const uint32_t* a,
                                        const uint32_t* b, const float* c) {
    asm volatile(
        "mma.sync.aligned.m16n8k16.row.col.f32.f16.f16.f32 "
        "{%0,%1,%2,%3}, {%4,%5,%6,%7}, {%8,%9}, {%10,%11,%12,%13};"
        : "=f"(d[0]), "=f"(d[1]), "=f"(d[2]), "=f"(d[3])
        : "r"(a[0]), "r"(a[1]), "r"(a[2]), "r"(a[3]),
          "r"(b[0]), "r"(b[1]),
          "f"(c[0]), "f"(c[1]), "f"(c[2]), "f"(c[3]));
}

__device__ __forceinline__ uint32_t smem_u32(const void* p) {
    uint32_t a;
    asm("{ .reg .u64 t; cvta.to.shared.u64 t, %1; cvt.u32.u64 %0, t; }" : "=r"(a) : "l"(p));
    return a;
}

__device__ __forceinline__ void ldmx4t(uint32_t& b0, uint32_t& b1,
                                       uint32_t& b2, uint32_t& b3, uint32_t addr) {
    asm volatile("ldmatrix.sync.aligned.m8n8.x4.trans.shared.b16 {%0,%1,%2,%3}, [%4];"
                 : "=r"(b0), "=r"(b1), "=r"(b2), "=r"(b3) : "r"(addr));
}

// ---------------------------------------------------------------------------
// GEMM body (R9-proven inner loop: scalar LDS fragments, software pipeline).
// C[m0:m0+128, cn0:cn0+128] = A[m0:, :K] @ B[:K, bn0:bn0+128]
// NB = B row stride, NC = C row stride. 256 threads, 8 warps (4m x 2n).
// ---------------------------------------------------------------------------
struct SmemGemm {
    uint32_t As[2][128][12];   // [buf][m][k2] packed half2 k-pairs
    uint32_t Bs[2][128][12];   // [buf][n][k2] (B transposed)
};

template <typename TOut>
__device__ __forceinline__ void gemm_body(
    SmemGemm& sm, const float* __restrict__ A, const float* __restrict__ B,
    TOut* __restrict__ C, int K, int NB, int NC, int m0, int bn0, int cn0) {

    const int tid = threadIdx.x;
    const int wid = tid >> 5;
    const int lane = tid & 31;
    const int g = lane >> 2;
    const int t = lane & 3;
    const int wm = (wid & 3) * 32;
    const int wn = (wid >> 2) * 64;

    const int aRow = tid >> 2;
    const int aK4  = (tid & 3) << 2;
    const int aK2  = (tid & 3) << 1;
    const int bN   = tid & 127;
    const int bKh  = tid >> 7;

    float acc[2][8][4];
#pragma unroll
    for (int mt = 0; mt < 2; ++mt)
#pragma unroll
        for (int nt = 0; nt < 8; ++nt)
#pragma unroll
            for (int r = 0; r < 4; ++r) acc[mt][nt][r] = 0.f;

    float4 ar[2];
    float  bv[4][2];

    // prologue: load + stage tile 0
#pragma unroll
    for (int l = 0; l < 2; ++l)
        ar[l] = *(const float4*)(A + (size_t)(m0 + aRow + l * 64) * K + aK4);
#pragma unroll
    for (int l = 0; l < 4; ++l) {
        int k2 = bKh + 2 * l;
        bv[l][0] = B[(size_t)(2 * k2) * NB + bn0 + bN];
        bv[l][1] = B[(size_t)(2 * k2 + 1) * NB + bn0 + bN];
    }
#pragma unroll
    for (int l = 0; l < 2; ++l)
        *(uint2*)(&sm.As[0][aRow + l * 64][aK2]) =
            make_uint2(pack2h(ar[l].x, ar[l].y), pack2h(ar[l].z, ar[l].w));
#pragma unroll
    for (int l = 0; l < 4; ++l)
        sm.Bs[0][bN][bKh + 2 * l] = pack2h(bv[l][0], bv[l][1]);
    __syncthreads();

    const int KT = K >> 4;
    for (int kt = 0; kt < KT; ++kt) {
        const int buf = kt & 1;

        // prefetch tile kt+1
        if (kt + 1 < KT) {
            const int k0n = (kt + 1) << 4;
#pragma unroll
            for (int l = 0; l < 2; ++l)
                ar[l] = *(const float4*)(A + (size_t)(m0 + aRow + l * 64) * K + k0n + aK4);
#pragma unroll
            for (int l = 0; l < 4; ++l) {
                int k2 = bKh + 2 * l;
                bv[l][0] = B[(size_t)(k0n + 2 * k2) * NB + bn0 + bN];
                bv[l][1] = B[(size_t)(k0n + 2 * k2 + 1) * NB + bn0 + bN];
            }
        }

        // compute tile kt (scalar LDS fragments — R9 proven)
        uint32_t af[2][4];
#pragma unroll
        for (int mt = 0; mt < 2; ++mt) {
            const int r0 = wm + mt * 16;
            af[mt][0] = sm.As[buf][r0 + g][t];
            af[mt][1] = sm.As[buf][r0 + g + 8][t];
            af[mt][2] = sm.As[buf][r0 + g][4 + t];
            af[mt][3] = sm.As[buf][r0 + g + 8][4 + t];
        }
#pragma unroll
        for (int nt = 0; nt < 8; ++nt) {
            const int n = wn + nt * 8 + g;
            uint32_t bf[2] = {sm.Bs[buf][n][t], sm.Bs[buf][n][4 + t]};
#pragma unroll
            for (int mt = 0; mt < 2; ++mt)
                mma_f16(acc[mt][nt], af[mt], bf, acc[mt][nt]);
        }

        // stage tile kt+1
        if (kt + 1 < KT) {
            const int nb = buf ^ 1;
#pragma unroll
            for (int l = 0; l < 2; ++l)
                *(uint2*)(&sm.As[nb][aRow + l * 64][aK2]) =
                    make_uint2(pack2h(ar[l].x, ar[l].y), pack2h(ar[l].z, ar[l].w));
#pragma unroll
            for (int l = 0; l < 4; ++l)
                sm.Bs[nb][bN][bKh + 2 * l] = pack2h(bv[l][0], bv[l][1]);
            __syncthreads();
        }
    }

    // epilogue
#pragma unroll
    for (int mt = 0; mt < 2; ++mt) {
        const int r0 = m0 + wm + mt * 16;
#pragma unroll
        for (int nt = 0; nt < 8; ++nt) {
            const int c0 = cn0 + wn + nt * 8 + t * 2;
            if (sizeof(TOut) == 4) {
                float* Cf = (float*)C;
                *(float2*)(Cf + (size_t)(r0 + g) * NC + c0) =
                    make_float2(acc[mt][nt][0], acc[mt][nt][1]);
                *(float2*)(Cf + (size_t)(r0 + g + 8) * NC + c0) =
                    make_float2(acc[mt][nt][2], acc[mt][nt][3]);
            } else {
                __half* Ch = (__half*)C;
                *(uint32_t*)(Ch + (size_t)(r0 + g) * NC + c0) =
                    pack2h(acc[mt][nt][0], acc[mt][nt][1]);
                *(uint32_t*)(Ch + (size_t)(r0 + g + 8) * NC + c0) =
                    pack2h(acc[mt][nt][2], acc[mt][nt][3]);
            }
        }
    }
}

// Generic single-matrix GEMM (used for the output projection)
template <typename TOut>
__global__ __launch_bounds__(256, 2)
void sgemm_f16(const float* __restrict__ A, const float* __restrict__ B,
               TOut* __restrict__ C, int M, int N, int K) {
    __shared__ SmemGemm sm;
    gemm_body<TOut>(sm, A, B, C, K, N, N, blockIdx.y * 128, blockIdx.x * 128,
                    blockIdx.x * 128);
}

// Fused Q/K/V projection: one launch, 24 n-tiles x 32 m-tiles = 768 CTAs.
__global__ __launch_bounds__(256, 2)
void sgemm_qkv(const float* __restrict__ x,
               const float* __restrict__ Wq, const float* __restrict__ Wk,
               const float* __restrict__ Wv,
               __half* __restrict__ q, __half* __restrict__ k,
               __half* __restrict__ v) {
    __shared__ SmemGemm sm;
    const int n0c = blockIdx.x * 128;
    const float* B;
    __half* C;
    int NB, n0;
    if (n0c < D_MODEL) {                 // Q: cols [0, 2048)
        B = Wq; C = q; NB = D_MODEL; n0 = n0c;
    } else if (n0c < D_MODEL + KV_DIM) { // K: cols [2048, 2560)
        B = Wk; C = k; NB = KV_DIM; n0 = n0c - D_MODEL;
    } else {                             // V: cols [2560, 3072)
        B = Wv; C = v; NB = KV_DIM; n0 = n0c - D_MODEL - KV_DIM;
    }
    gemm_body<__half>(sm, x, B, C, D_MODEL, NB, NB, blockIdx.y * 128, n0, n0);
}

// ---------------------------------------------------------------------------
// RoPE in-place on fp16 [T, nheads, 128] buffers (rowstride in halves).
// ---------------------------------------------------------------------------
__global__ void rope_kernel_h(__half* __restrict__ buf, int nheads, int rowstride) {
    int idx = blockIdx.x * blockDim.x + threadIdx.x;
    int total = T_SEQ * nheads * 32;        // 32 half2 pairs per (t,h)
    if (idx >= total) return;
    int i2 = idx & 31;
    int h = (idx >> 5) % nheads;
    int t = idx / (32 * nheads);

    float i0 = (float)(2 * i2);
    float i1 = (float)(2 * i2 + 1);
    float inv0 = powf(10000.f, -i0 / (float)HALF);
    float inv1 = powf(10000.f, -i1 / (float)HALF);
    float s0, c0, s1, c1;
    sincosf((float)t * inv0, &s0, &c0);
    sincosf((float)t * inv1, &s1, &c1);

    __half* base = buf + (size_t)t * rowstride + h * DH;
    float2 x1 = __half22float2(*(__half2*)(base + 2 * i2));
    float2 x2 = __half22float2(*(__half2*)(base + HALF + 2 * i2));
    *(__half2*)(base + 2 * i2) =
        __floats2half2_rn(x1.x * c0 - x2.x * s0, x1.y * c1 - x2.y * s1);
    *(__half2*)(base + HALF + 2 * i2) =
        __floats2half2_rn(x1.x * s0 + x2.x * c0, x1.y * s1 + x2.y * c1);
}

// ---------------------------------------------------------------------------
// Flash attention (all fp16 mma, fp16 inputs — staging is a pure copy).
// Unchanged from R11. CTA = 64 q x 1 head, 128 threads / 4 warps.
// ---------------------------------------------------------------------------
#define AOQ 0
#define AOK 4352
#define AOV 8704
#define ATTN_SMEM_BYTES ((8704 + 4352) * 4)   // 52224

__global__ __launch_bounds__(128)
void attn_kernel(const __half* __restrict__ q, const __half* __restrict__ k,
                 const __half* __restrict__ v, float* __restrict__ y) {
    extern __shared__ uint32_t smu[];
    uint32_t* Qh = smu + AOQ;              // [64][68] half2 pairs along d
    uint32_t* Kh = smu + AOK;              // [64][68]
    __half*   Vh = (__half*)(smu + AOV);   // [64][136] row-major [key][d]

    const int qb = blockIdx.x;
    const int hq = blockIdx.y;
    const int hkv = hq >> 2;
    const int q0 = qb * 64;
    const int tid = threadIdx.x;
    const int wid = tid >> 5;
    const int lane = tid & 31;
    const int g = lane >> 2;
    const int t = lane & 3;
    const int r0 = wid * 16;
    const int rg0 = q0 + r0 + g;
    const int rg1 = rg0 + 8;

    // stage Q once (pure uint4 copy)
#pragma unroll
    for (int l = 0; l < 8; ++l) {
        int lin = tid + l * 128;
        int row = lin >> 4;
        int d8 = lin & 15;
        uint4 u = *(const uint4*)(q + (size_t)(q0 + row) * D_MODEL + hq * DH + d8 * 8);
        *(uint4*)(Qh + row * 68 + d8 * 4) = u;
    }

    float acc[16][4];
#pragma unroll
    for (int n = 0; n < 16; ++n)
#pragma unroll
        for (int r = 0; r < 4; ++r) acc[n][r] = 0.f;
    float m_i[2] = {-1e30f, -1e30f};
    float l_i[2] = {0.f, 0.f};

    const float scale = 0.08838834764831845f;   // 1/sqrt(128)

    for (int jb = 0; jb <= qb; ++jb) {
        const int j0 = jb * 64;
        __syncthreads();

        // stage K + V (pure uint4 copies)
#pragma unroll
        for (int l = 0; l < 8; ++l) {
            int lin = tid + l * 128;
            int row = lin >> 4;
            int d8 = lin & 15;
            uint4 ku = *(const uint4*)(k + (size_t)(j0 + row) * KV_DIM + hkv * DH + d8 * 8);
            *(uint4*)(Kh + row * 68 + d8 * 4) = ku;
            uint4 vu = *(const uint4*)(v + (size_t)(j0 + row) * KV_DIM + hkv * DH + d8 * 8);
            *(uint4*)(Vh + row * 136 + d8 * 8) = vu;
        }
        __syncthreads();

        if (j0 > q0 + r0 + 15) continue;

        // S = Q K^T
        float sf[8][4];
#pragma unroll
        for (int nt = 0; nt < 8; ++nt)
#pragma unroll
            for (int r = 0; r < 4; ++r) sf[nt][r] = 0.f;

        const uint32_t* qr0 = Qh + (r0 + g) * 68;
        const uint32_t* qr1 = Qh + (r0 + g + 8) * 68;
#pragma unroll
        for (int ks = 0; ks < 8; ++ks) {
            const int kk = ks * 8;
            uint32_t a[4] = {qr0[kk + t], qr1[kk + t], qr0[kk + 4 + t], qr1[kk + 4 + t]};
#pragma unroll
            for (int nt = 0; nt < 8; ++nt) {
                const uint32_t* kr = Kh + (nt * 8 + g) * 68 + kk;
                uint32_t b[2] = {kr[t], kr[4 + t]};
                mma_f16(sf[nt], a, b, sf[nt]);
            }
        }

        // scale + causal mask
#pragma unroll
        for (int nt = 0; nt < 8; ++nt) {
            sf[nt][0] *= scale; sf[nt][1] *= scale;
            sf[nt][2] *= scale; sf[nt][3] *= scale;
        }
        if (j0 + 63 > rg0) {
#pragma unroll
            for (int nt = 0; nt < 8; ++nt) {
                const int c = j0 + nt * 8 + 2 * t;
                if (c     > rg0) sf[nt][0] = -1e30f;
                if (c + 1 > rg0) sf[nt][1] = -1e30f;
                if (c     > rg1) sf[nt][2] = -1e30f;
                if (c + 1 > rg1) sf[nt][3] = -1e30f;
            }
        }

        // online softmax (quad-local)
        float mx0 = -1e30f, mx1 = -1e30f;
#pragma unroll
        for (int nt = 0; nt < 8; ++nt) {
            mx0 = fmaxf(mx0, fmaxf(sf[nt][0], sf[nt][1]));
            mx1 = fmaxf(mx1, fmaxf(sf[nt][2], sf[nt][3]));
        }
        mx0 = fmaxf(mx0, __shfl_xor_sync(0xffffffffu, mx0, 1));
        mx0 = fmaxf(mx0, __shfl_xor_sync(0xffffffffu, mx0, 2));
        mx1 = fmaxf(mx1, __shfl_xor_sync(0xffffffffu, mx1, 1));
        mx1 = fmaxf(mx1, __shfl_xor_sync(0xffffffffu, mx1, 2));

        const float mn0 = fmaxf(m_i[0], mx0);
        const float mn1 = fmaxf(m_i[1], mx1);
        const float al0 = __expf(m_i[0] - mn0);
        const float al1 = __expf(m_i[1] - mn1);

        float sum0 = 0.f, sum1 = 0.f;
#pragma unroll
        for (int nt = 0; nt < 8; ++nt) {
            sf[nt][0] = __expf(sf[nt][0] - mn0);
            sf[nt][1] = __expf(sf[nt][1] - mn0);
            sf[nt][2] = __expf(sf[nt][2] - mn1);
            sf[nt][3] = __expf(sf[nt][3] - mn1);
            sum0 += sf[nt][0] + sf[nt][1];
            sum1 += sf[nt][2] + sf[nt][3];
        }
        sum0 += __shfl_xor_sync(0xffffffffu, sum0, 1);
        sum0 += __shfl_xor_sync(0xffffffffu, sum0, 2);
        sum1 += __shfl_xor_sync(0xffffffffu, sum1, 1);
        sum1 += __shfl_xor_sync(0xffffffffu, sum1, 2);

        l_i[0] = l_i[0] * al0 + sum0;
        l_i[1] = l_i[1] * al1 + sum1;
        m_i[0] = mn0;
        m_i[1] = mn1;

#pragma unroll
        for (int n = 0; n < 16; ++n) {
            acc[n][0] *= al0; acc[n][1] *= al0;
            acc[n][2] *= al1; acc[n][3] *= al1;
        }

        // O += P V
        const int vrow = lane & 15;
        const int vcol8 = (lane >> 4) * 8;
#pragma unroll
        for (int ks = 0; ks < 4; ++ks) {
            uint32_t a[4] = {pack2h(sf[2 * ks][0],     sf[2 * ks][1]),
                             pack2h(sf[2 * ks][2],     sf[2 * ks][3]),
                             pack2h(sf[2 * ks + 1][0], sf[2 * ks + 1][1]),
                             pack2h(sf[2 * ks + 1][2], sf[2 * ks + 1][3])};
            const __half* vbase = Vh + (16 * ks + vrow) * 136 + vcol8;
#pragma unroll
            for (int ntp = 0; ntp < 8; ++ntp) {
                uint32_t b0, b1, b2, b3;
                ldmx4t(b0, b1, b2, b3, smem_u32(vbase + ntp * 16));
                uint32_t blo[2] = {b0, b1};
                uint32_t bhi[2] = {b2, b3};
                mma_f16(acc[2 * ntp],     a, blo, acc[2 * ntp]);
                mma_f16(acc[2 * ntp + 1], a, bhi, acc[2 * ntp + 1]);
            }
        }
    }

    // normalize + write
    const float i0 = 1.f / l_i[0];
    const float i1 = 1.f / l_i[1];
    float* y0 = y + (size_t)rg0 * D_MODEL + hq * DH;
    float* y1 = y + (size_t)rg1 * D_MODEL + hq * DH;
#pragma unroll
    for (int n = 0; n < 16; ++n) {
        const int c0 = n * 8 + 2 * t;
        *(float2*)(y0 + c0) = make_float2(acc[n][0] * i0, acc[n][1] * i0);
        *(float2*)(y1 + c0) = make_float2(acc[n][2] * i1, acc[n][3] * i1);
    }
}

// ---------------------------------------------------------------------------
extern "C" void kernel_launch(void* const* d_in, const int* in_sizes, int n_in,
                              void* d_out, int out_size) {
    const float* x  = (const float*)d_in[0];
    const float* Wq = (const float*)d_in[1];
    const float* Wk = (const float*)d_in[2];
    const float* Wv = (const float*)d_in[3];
    const float* Wo = (const float*)d_in[4];
    float* out = (float*)d_out;

    void *pq, *pk, *pv, *py;
    cudaGetSymbolAddress(&pq, g_qh);
    cudaGetSymbolAddress(&pk, g_kh);
    cudaGetSymbolAddress(&pv, g_vh);
    cudaGetSymbolAddress(&py, g_y);
    __half* qh = (__half*)pq;
    __half* kh = (__half*)pk;
    __half* vh = (__half*)pv;
    float*  y  = (float*)py;

    // Fused Q/K/V projections: one launch, 768 CTAs
    sgemm_qkv<<<dim3((D_MODEL + 2 * KV_DIM) / 128, T_SEQ / 128), 256>>>(
        x, Wq, Wk, Wv, qh, kh, vh);

    // RoPE on fp16 buffers
    {
        int nq = T_SEQ * N_HEADS * 32;
        rope_kernel_h<<<(nq + 255) / 256, 256>>>(qh, N_HEADS, D_MODEL);
        int nk = T_SEQ * N_KV * 32;
        rope_kernel_h<<<(nk + 255) / 256, 256>>>(kh, N_KV, KV_DIM);
    }

    // Attention (all-mma, fp16 inputs)
    cudaFuncSetAttribute(attn_kernel, cudaFuncAttributeMaxDynamicSharedMemorySize, ATTN_SMEM_BYTES);
    attn_kernel<<<dim3(T_SEQ / 64, N_HEADS), 128, ATTN_SMEM_BYTES>>>(qh, kh, vh, y);

    // Output projection (fp32 output)
    sgemm_f16<float><<<dim3(D_MODEL / 128, T_SEQ / 128), 256>>>(y, Wo, out, T_SEQ, D_MODEL, D_MODEL);
}

// round 13
// speedup vs baseline: 1.0868x; 1.0026x over previous
#include <cuda_runtime.h>
#include <cuda_fp16.h>
#include <math.h>
#include <cstdint>

// Problem constants
#define T_SEQ 4096
#define D_MODEL 2048
#define N_HEADS 16
#define N_KV 4
#define DH 128
#define HALF 64
#define KV_DIM 512   // N_KV * DH

// Scratch (device globals; no allocation allowed)
__device__ __half g_qh[T_SEQ * D_MODEL];
__device__ __half g_kh[T_SEQ * KV_DIM];
__device__ __half g_vh[T_SEQ * KV_DIM];
__device__ float  g_y[T_SEQ * D_MODEL];

// ---------------------------------------------------------------------------
// helpers
// ---------------------------------------------------------------------------
__device__ __forceinline__ uint32_t pack2h(float lo, float hi) {
    __half2 h = __floats2half2_rn(lo, hi);   // .x = lo -> low 16 bits
    return *(uint32_t*)&h;
}

__device__ __forceinline__ void mma_f16(float* d, const uint32_t* a,
                                        const uint32_t* b, const float* c) {
    asm volatile(
        "mma.sync.aligned.m16n8k16.row.col.f32.f16.f16.f32 "
        "{%0,%1,%2,%3}, {%4,%5,%6,%7}, {%8,%9}, {%10,%11,%12,%13};"
        : "=f"(d[0]), "=f"(d[1]), "=f"(d[2]), "=f"(d[3])
        : "r"(a[0]), "r"(a[1]), "r"(a[2]), "r"(a[3]),
          "r"(b[0]), "r"(b[1]),
          "f"(c[0]), "f"(c[1]), "f"(c[2]), "f"(c[3]));
}

__device__ __forceinline__ uint32_t smem_u32(const void* p) {
    uint32_t a;
    asm("{ .reg .u64 t; cvta.to.shared.u64 t, %1; cvt.u32.u64 %0, t; }" : "=r"(a) : "l"(p));
    return a;
}

__device__ __forceinline__ void ldmx4t(uint32_t& b0, uint32_t& b1,
                                       uint32_t& b2, uint32_t& b3, uint32_t addr) {
    asm volatile("ldmatrix.sync.aligned.m8n8.x4.trans.shared.b16 {%0,%1,%2,%3}, [%4];"
                 : "=r"(b0), "=r"(b1), "=r"(b2), "=r"(b3) : "r"(addr));
}

__device__ __forceinline__ void cpa16(uint32_t dst, const void* src) {
    asm volatile("cp.async.cg.shared.global [%0], [%1], 16;" :: "r"(dst), "l"(src));
}
__device__ __forceinline__ void cpa_commit() {
    asm volatile("cp.async.commit_group;" ::: "memory");
}
template <int N>
__device__ __forceinline__ void cpa_wait() {
    asm volatile("cp.async.wait_group %0;" :: "n"(N) : "memory");
}

// ---------------------------------------------------------------------------
// GEMM body (R9-proven inner loop) — unchanged from R12.
// ---------------------------------------------------------------------------
struct SmemGemm {
    uint32_t As[2][128][12];   // [buf][m][k2] packed half2 k-pairs
    uint32_t Bs[2][128][12];   // [buf][n][k2] (B transposed)
};

template <typename TOut>
__device__ __forceinline__ void gemm_body(
    SmemGemm& sm, const float* __restrict__ A, const float* __restrict__ B,
    TOut* __restrict__ C, int K, int NB, int NC, int m0, int bn0, int cn0) {

    const int tid = threadIdx.x;
    const int wid = tid >> 5;
    const int lane = tid & 31;
    const int g = lane >> 2;
    const int t = lane & 3;
    const int wm = (wid & 3) * 32;
    const int wn = (wid >> 2) * 64;

    const int aRow = tid >> 2;
    const int aK4  = (tid & 3) << 2;
    const int aK2  = (tid & 3) << 1;
    const int bN   = tid & 127;
    const int bKh  = tid >> 7;

    float acc[2][8][4];
#pragma unroll
    for (int mt = 0; mt < 2; ++mt)
#pragma unroll
        for (int nt = 0; nt < 8; ++nt)
#pragma unroll
            for (int r = 0; r < 4; ++r) acc[mt][nt][r] = 0.f;

    float4 ar[2];
    float  bv[4][2];

#pragma unroll
    for (int l = 0; l < 2; ++l)
        ar[l] = *(const float4*)(A + (size_t)(m0 + aRow + l * 64) * K + aK4);
#pragma unroll
    for (int l = 0; l < 4; ++l) {
        int k2 = bKh + 2 * l;
        bv[l][0] = B[(size_t)(2 * k2) * NB + bn0 + bN];
        bv[l][1] = B[(size_t)(2 * k2 + 1) * NB + bn0 + bN];
    }
#pragma unroll
    for (int l = 0; l < 2; ++l)
        *(uint2*)(&sm.As[0][aRow + l * 64][aK2]) =
            make_uint2(pack2h(ar[l].x, ar[l].y), pack2h(ar[l].z, ar[l].w));
#pragma unroll
    for (int l = 0; l < 4; ++l)
        sm.Bs[0][bN][bKh + 2 * l] = pack2h(bv[l][0], bv[l][1]);
    __syncthreads();

    const int KT = K >> 4;
    for (int kt = 0; kt < KT; ++kt) {
        const int buf = kt & 1;

        if (kt + 1 < KT) {
            const int k0n = (kt + 1) << 4;
#pragma unroll
            for (int l = 0; l < 2; ++l)
                ar[l] = *(const float4*)(A + (size_t)(m0 + aRow + l * 64) * K + k0n + aK4);
#pragma unroll
            for (int l = 0; l < 4; ++l) {
                int k2 = bKh + 2 * l;
                bv[l][0] = B[(size_t)(k0n + 2 * k2) * NB + bn0 + bN];
                bv[l][1] = B[(size_t)(k0n + 2 * k2 + 1) * NB + bn0 + bN];
            }
        }

        uint32_t af[2][4];
#pragma unroll
        for (int mt = 0; mt < 2; ++mt) {
            const int r0 = wm + mt * 16;
            af[mt][0] = sm.As[buf][r0 + g][t];
            af[mt][1] = sm.As[buf][r0 + g + 8][t];
            af[mt][2] = sm.As[buf][r0 + g][4 + t];
            af[mt][3] = sm.As[buf][r0 + g + 8][4 + t];
        }
#pragma unroll
        for (int nt = 0; nt < 8; ++nt) {
            const int n = wn + nt * 8 + g;
            uint32_t bf[2] = {sm.Bs[buf][n][t], sm.Bs[buf][n][4 + t]};
#pragma unroll
            for (int mt = 0; mt < 2; ++mt)
                mma_f16(acc[mt][nt], af[mt], bf, acc[mt][nt]);
        }

        if (kt + 1 < KT) {
            const int nb = buf ^ 1;
#pragma unroll
            for (int l = 0; l < 2; ++l)
                *(uint2*)(&sm.As[nb][aRow + l * 64][aK2]) =
                    make_uint2(pack2h(ar[l].x, ar[l].y), pack2h(ar[l].z, ar[l].w));
#pragma unroll
            for (int l = 0; l < 4; ++l)
                sm.Bs[nb][bN][bKh + 2 * l] = pack2h(bv[l][0], bv[l][1]);
            __syncthreads();
        }
    }

#pragma unroll
    for (int mt = 0; mt < 2; ++mt) {
        const int r0 = m0 + wm + mt * 16;
#pragma unroll
        for (int nt = 0; nt < 8; ++nt) {
            const int c0 = cn0 + wn + nt * 8 + t * 2;
            if (sizeof(TOut) == 4) {
                float* Cf = (float*)C;
                *(float2*)(Cf + (size_t)(r0 + g) * NC + c0) =
                    make_float2(acc[mt][nt][0], acc[mt][nt][1]);
                *(float2*)(Cf + (size_t)(r0 + g + 8) * NC + c0) =
                    make_float2(acc[mt][nt][2], acc[mt][nt][3]);
            } else {
                __half* Ch = (__half*)C;
                *(uint32_t*)(Ch + (size_t)(r0 + g) * NC + c0) =
                    pack2h(acc[mt][nt][0], acc[mt][nt][1]);
                *(uint32_t*)(Ch + (size_t)(r0 + g + 8) * NC + c0) =
                    pack2h(acc[mt][nt][2], acc[mt][nt][3]);
            }
        }
    }
}

template <typename TOut>
__global__ __launch_bounds__(256, 2)
void sgemm_f16(const float* __restrict__ A, const float* __restrict__ B,
               TOut* __restrict__ C, int M, int N, int K) {
    __shared__ SmemGemm sm;
    gemm_body<TOut>(sm, A, B, C, K, N, N, blockIdx.y * 128, blockIdx.x * 128,
                    blockIdx.x * 128);
}

__global__ __launch_bounds__(256, 2)
void sgemm_qkv(const float* __restrict__ x,
               const float* __restrict__ Wq, const float* __restrict__ Wk,
               const float* __restrict__ Wv,
               __half* __restrict__ q, __half* __restrict__ k,
               __half* __restrict__ v) {
    __shared__ SmemGemm sm;
    const int n0c = blockIdx.x * 128;
    const float* B;
    __half* C;
    int NB, n0;
    if (n0c < D_MODEL) {
        B = Wq; C = q; NB = D_MODEL; n0 = n0c;
    } else if (n0c < D_MODEL + KV_DIM) {
        B = Wk; C = k; NB = KV_DIM; n0 = n0c - D_MODEL;
    } else {
        B = Wv; C = v; NB = KV_DIM; n0 = n0c - D_MODEL - KV_DIM;
    }
    gemm_body<__half>(sm, x, B, C, D_MODEL, NB, NB, blockIdx.y * 128, n0, n0);
}

// ---------------------------------------------------------------------------
// RoPE in-place on fp16 [T, nheads, 128] buffers (rowstride in halves).
// ---------------------------------------------------------------------------
__global__ void rope_kernel_h(__half* __restrict__ buf, int nheads, int rowstride) {
    int idx = blockIdx.x * blockDim.x + threadIdx.x;
    int total = T_SEQ * nheads * 32;
    if (idx >= total) return;
    int i2 = idx & 31;
    int h = (idx >> 5) % nheads;
    int t = idx / (32 * nheads);

    float i0 = (float)(2 * i2);
    float i1 = (float)(2 * i2 + 1);
    float inv0 = powf(10000.f, -i0 / (float)HALF);
    float inv1 = powf(10000.f, -i1 / (float)HALF);
    float s0, c0, s1, c1;
    sincosf((float)t * inv0, &s0, &c0);
    sincosf((float)t * inv1, &s1, &c1);

    __half* base = buf + (size_t)t * rowstride + h * DH;
    float2 x1 = __half22float2(*(__half2*)(base + 2 * i2));
    float2 x2 = __half22float2(*(__half2*)(base + HALF + 2 * i2));
    *(__half2*)(base + 2 * i2) =
        __floats2half2_rn(x1.x * c0 - x2.x * s0, x1.y * c1 - x2.y * s1);
    *(__half2*)(base + HALF + 2 * i2) =
        __floats2half2_rn(x1.x * s0 + x2.x * c0, x1.y * s1 + x2.y * c1);
}

// ---------------------------------------------------------------------------
// Flash attention v6: all fp16 mma + double-buffered cp.async K/V staging +
// heavy-blocks-first scheduling. CTA = 64 q x 1 head, 128 threads / 4 warps.
// Smem (u32): Qh[64][68], K0/K1[64][68], V0/V1[64][68 u32 = 136 halves].
// ---------------------------------------------------------------------------
#define AOQ 0
#define AOK0 4352
#define AOK1 8704
#define AOV0 13056
#define AOV1 17408
#define ATTN_SMEM_BYTES (21760 * 4)   // 87040

__global__ __launch_bounds__(128)
void attn_kernel(const __half* __restrict__ q, const __half* __restrict__ k,
                 const __half* __restrict__ v, float* __restrict__ y) {
    extern __shared__ uint32_t smu[];
    uint32_t* Qh = smu + AOQ;

    const int qb = (gridDim.x - 1) - blockIdx.x;   // heavy blocks first
    const int hq = blockIdx.y;
    const int hkv = hq >> 2;
    const int q0 = qb * 64;
    const int tid = threadIdx.x;
    const int wid = tid >> 5;
    const int lane = tid & 31;
    const int g = lane >> 2;
    const int t = lane & 3;
    const int r0 = wid * 16;
    const int rg0 = q0 + r0 + g;
    const int rg1 = rg0 + 8;

    // staging chunk indices (8 K + 8 V chunks of 16B per thread)
    const int sRow = tid >> 4;              // base row 0..7 (+8 per l)
    const int sD16 = tid & 15;              // 16B chunk within 256B row

    const uint32_t kBase[2] = {smem_u32(smu + AOK0), smem_u32(smu + AOK1)};
    const uint32_t vBase[2] = {smem_u32(smu + AOV0), smem_u32(smu + AOV1)};

    // ---- stage Q once (pure uint4 copy)
#pragma unroll
    for (int l = 0; l < 8; ++l) {
        int lin = tid + l * 128;
        int row = lin >> 4;
        int d8 = lin & 15;
        uint4 u = *(const uint4*)(q + (size_t)(q0 + row) * D_MODEL + hq * DH + d8 * 8);
        *(uint4*)(Qh + row * 68 + d8 * 4) = u;
    }

    // ---- issue async K/V for block 0 into buffer 0
    {
        const __half* kp = k + (size_t)0 * KV_DIM + hkv * DH;
        const __half* vp = v + (size_t)0 * KV_DIM + hkv * DH;
#pragma unroll
        for (int l = 0; l < 8; ++l) {
            int row = sRow + l * 8;
            cpa16(kBase[0] + row * 272 + sD16 * 16,
                  kp + (size_t)row * KV_DIM + sD16 * 8);
            cpa16(vBase[0] + row * 272 + sD16 * 16,
                  vp + (size_t)row * KV_DIM + sD16 * 8);
        }
        cpa_commit();
    }

    float acc[16][4];
#pragma unroll
    for (int n = 0; n < 16; ++n)
#pragma unroll
        for (int r = 0; r < 4; ++r) acc[n][r] = 0.f;
    float m_i[2] = {-1e30f, -1e30f};
    float l_i[2] = {0.f, 0.f};

    const float scale = 0.08838834764831845f;   // 1/sqrt(128)

    for (int jb = 0; jb <= qb; ++jb) {
        const int j0 = jb * 64;
        const int buf = jb & 1;
        __syncthreads();   // previous compute done before its buffer is overwritten

        // ---- issue async K/V for block jb+1 into the other buffer
        if (jb < qb) {
            const int jn = (jb + 1) * 64;
            const int nb = buf ^ 1;
            const __half* kp = k + (size_t)jn * KV_DIM + hkv * DH;
            const __half* vp = v + (size_t)jn * KV_DIM + hkv * DH;
#pragma unroll
            for (int l = 0; l < 8; ++l) {
                int row = sRow + l * 8;
                cpa16(kBase[nb] + row * 272 + sD16 * 16,
                      kp + (size_t)row * KV_DIM + sD16 * 8);
                cpa16(vBase[nb] + row * 272 + sD16 * 16,
                      vp + (size_t)row * KV_DIM + sD16 * 8);
            }
            cpa_commit();
            cpa_wait<1>();   // block jb's group complete
        } else {
            cpa_wait<0>();
        }
        __syncthreads();     // completed copies visible to all warps

        if (j0 > q0 + r0 + 15) continue;   // warp fully above this key block

        const uint32_t* Kh = smu + (buf ? AOK1 : AOK0);
        const __half*   Vh = (const __half*)(smu + (buf ? AOV1 : AOV0));

        // ---- S = Q K^T
        float sf[8][4];
#pragma unroll
        for (int nt = 0; nt < 8; ++nt)
#pragma unroll
            for (int r = 0; r < 4; ++r) sf[nt][r] = 0.f;

        const uint32_t* qr0 = Qh + (r0 + g) * 68;
        const uint32_t* qr1 = Qh + (r0 + g + 8) * 68;
#pragma unroll
        for (int ks = 0; ks < 8; ++ks) {
            const int kk = ks * 8;
            uint32_t a[4] = {qr0[kk + t], qr1[kk + t], qr0[kk + 4 + t], qr1[kk + 4 + t]};
#pragma unroll
            for (int nt = 0; nt < 8; ++nt) {
                const uint32_t* kr = Kh + (nt * 8 + g) * 68 + kk;
                uint32_t b[2] = {kr[t], kr[4 + t]};
                mma_f16(sf[nt], a, b, sf[nt]);
            }
        }

        // ---- scale + causal mask
#pragma unroll
        for (int nt = 0; nt < 8; ++nt) {
            sf[nt][0] *= scale; sf[nt][1] *= scale;
            sf[nt][2] *= scale; sf[nt][3] *= scale;
        }
        if (j0 + 63 > rg0) {
#pragma unroll
            for (int nt = 0; nt < 8; ++nt) {
                const int c = j0 + nt * 8 + 2 * t;
                if (c     > rg0) sf[nt][0] = -1e30f;
                if (c + 1 > rg0) sf[nt][1] = -1e30f;
                if (c     > rg1) sf[nt][2] = -1e30f;
                if (c + 1 > rg1) sf[nt][3] = -1e30f;
            }
        }

        // ---- online softmax (quad-local)
        float mx0 = -1e30f, mx1 = -1e30f;
#pragma unroll
        for (int nt = 0; nt < 8; ++nt) {
            mx0 = fmaxf(mx0, fmaxf(sf[nt][0], sf[nt][1]));
            mx1 = fmaxf(mx1, fmaxf(sf[nt][2], sf[nt][3]));
        }
        mx0 = fmaxf(mx0, __shfl_xor_sync(0xffffffffu, mx0, 1));
        mx0 = fmaxf(mx0, __shfl_xor_sync(0xffffffffu, mx0, 2));
        mx1 = fmaxf(mx1, __shfl_xor_sync(0xffffffffu, mx1, 1));
        mx1 = fmaxf(mx1, __shfl_xor_sync(0xffffffffu, mx1, 2));

        const float mn0 = fmaxf(m_i[0], mx0);
        const float mn1 = fmaxf(m_i[1], mx1);
        const float al0 = __expf(m_i[0] - mn0);
        const float al1 = __expf(m_i[1] - mn1);

        float sum0 = 0.f, sum1 = 0.f;
#pragma unroll
        for (int nt = 0; nt < 8; ++nt) {
            sf[nt][0] = __expf(sf[nt][0] - mn0);
            sf[nt][1] = __expf(sf[nt][1] - mn0);
            sf[nt][2] = __expf(sf[nt][2] - mn1);
            sf[nt][3] = __expf(sf[nt][3] - mn1);
            sum0 += sf[nt][0] + sf[nt][1];
            sum1 += sf[nt][2] + sf[nt][3];
        }
        sum0 += __shfl_xor_sync(0xffffffffu, sum0, 1);
        sum0 += __shfl_xor_sync(0xffffffffu, sum0, 2);
        sum1 += __shfl_xor_sync(0xffffffffu, sum1, 1);
        sum1 += __shfl_xor_sync(0xffffffffu, sum1, 2);

        l_i[0] = l_i[0] * al0 + sum0;
        l_i[1] = l_i[1] * al1 + sum1;
        m_i[0] = mn0;
        m_i[1] = mn1;

#pragma unroll
        for (int n = 0; n < 16; ++n) {
            acc[n][0] *= al0; acc[n][1] *= al0;
            acc[n][2] *= al1; acc[n][3] *= al1;
        }

        // ---- O += P V
        const int vrow = lane & 15;
        const int vcol8 = (lane >> 4) * 8;
#pragma unroll
        for (int ks = 0; ks < 4; ++ks) {
            uint32_t a[4] = {pack2h(sf[2 * ks][0],     sf[2 * ks][1]),
                             pack2h(sf[2 * ks][2],     sf[2 * ks][3]),
                             pack2h(sf[2 * ks + 1][0], sf[2 * ks + 1][1]),
                             pack2h(sf[2 * ks + 1][2], sf[2 * ks + 1][3])};
            const __half* vbase = Vh + (16 * ks + vrow) * 136 + vcol8;
#pragma unroll
            for (int ntp = 0; ntp < 8; ++ntp) {
                uint32_t b0, b1, b2, b3;
                ldmx4t(b0, b1, b2, b3, smem_u32(vbase + ntp * 16));
                uint32_t blo[2] = {b0, b1};
                uint32_t bhi[2] = {b2, b3};
                mma_f16(acc[2 * ntp],     a, blo, acc[2 * ntp]);
                mma_f16(acc[2 * ntp + 1], a, bhi, acc[2 * ntp + 1]);
            }
        }
    }

    // ---- normalize + write
    const float i0 = 1.f / l_i[0];
    const float i1 = 1.f / l_i[1];
    float* y0 = y + (size_t)rg0 * D_MODEL + hq * DH;
    float* y1 = y + (size_t)rg1 * D_MODEL + hq * DH;
#pragma unroll
    for (int n = 0; n < 16; ++n) {
        const int c0 = n * 8 + 2 * t;
        *(float2*)(y0 + c0) = make_float2(acc[n][0] * i0, acc[n][1] * i0);
        *(float2*)(y1 + c0) = make_float2(acc[n][2] * i1, acc[n][3] * i1);
    }
}

// ---------------------------------------------------------------------------
extern "C" void kernel_launch(void* const* d_in, const int* in_sizes, int n_in,
                              void* d_out, int out_size) {
    const float* x  = (const float*)d_in[0];
    const float* Wq = (const float*)d_in[1];
    const float* Wk = (const float*)d_in[2];
    const float* Wv = (const float*)d_in[3];
    const float* Wo = (const float*)d_in[4];
    float* out = (float*)d_out;

    void *pq, *pk, *pv, *py;
    cudaGetSymbolAddress(&pq, g_qh);
    cudaGetSymbolAddress(&pk, g_kh);
    cudaGetSymbolAddress(&pv, g_vh);
    cudaGetSymbolAddress(&py, g_y);
    __half* qh = (__half*)pq;
    __half* kh = (__half*)pk;
    __half* vh = (__half*)pv;
    float*  y  = (float*)py;

    // Fused Q/K/V projections: one launch, 768 CTAs
    sgemm_qkv<<<dim3((D_MODEL + 2 * KV_DIM) / 128, T_SEQ / 128), 256>>>(
        x, Wq, Wk, Wv, qh, kh, vh);

    // RoPE on fp16 buffers
    {
        int nq = T_SEQ * N_HEADS * 32;
        rope_kernel_h<<<(nq + 255) / 256, 256>>>(qh, N_HEADS, D_MODEL);
        int nk = T_SEQ * N_KV * 32;
        rope_kernel_h<<<(nk + 255) / 256, 256>>>(kh, N_KV, KV_DIM);
    }

    // Attention (all-mma, cp.async double-buffered, heavy-first)
    cudaFuncSetAttribute(attn_kernel, cudaFuncAttributeMaxDynamicSharedMemorySize, ATTN_SMEM_BYTES);
    attn_kernel<<<dim3(T_SEQ / 64, N_HEADS), 128, ATTN_SMEM_BYTES>>>(qh, kh, vh, y);

    // Output projection (fp32 output)
    sgemm_f16<float><<<dim3(D_MODEL / 128, T_SEQ / 128), 256>>>(y, Wo, out, T_SEQ, D_MODEL, D_MODEL);
}

// round 14
// speedup vs baseline: 1.1648x; 1.0717x over previous
#include <cuda_runtime.h>
#include <cuda_fp16.h>
#include <math.h>
#include <cstdint>

// Problem constants
#define T_SEQ 4096
#define D_MODEL 2048
#define N_HEADS 16
#define N_KV 4
#define DH 128
#define HALF 64
#define KV_DIM 512   // N_KV * DH

// Scratch (device globals; no allocation allowed)
__device__ __half g_qh[T_SEQ * D_MODEL];
__device__ __half g_kh[T_SEQ * KV_DIM];
__device__ __half g_vh[T_SEQ * KV_DIM];
__device__ float  g_y[T_SEQ * D_MODEL];

// ---------------------------------------------------------------------------
// helpers
// ---------------------------------------------------------------------------
__device__ __forceinline__ uint32_t pack2h(float lo, float hi) {
    __half2 h = __floats2half2_rn(lo, hi);   // .x = lo -> low 16 bits
    return *(uint32_t*)&h;
}

__device__ __forceinline__ void mma_f16(float* d, const uint32_t* a,
                                        const uint32_t* b, const float* c) {
    asm volatile(
        "mma.sync.aligned.m16n8k16.row.col.f32.f16.f16.f32 "
        "{%0,%1,%2,%3}, {%4,%5,%6,%7}, {%8,%9}, {%10,%11,%12,%13};"
        : "=f"(d[0]), "=f"(d[1]), "=f"(d[2]), "=f"(d[3])
        : "r"(a[0]), "r"(a[1]), "r"(a[2]), "r"(a[3]),
          "r"(b[0]), "r"(b[1]),
          "f"(c[0]), "f"(c[1]), "f"(c[2]), "f"(c[3]));
}

__device__ __forceinline__ uint32_t smem_u32(const void* p) {
    uint32_t a;
    asm("{ .reg .u64 t; cvta.to.shared.u64 t, %1; cvt.u32.u64 %0, t; }" : "=r"(a) : "l"(p));
    return a;
}

__device__ __forceinline__ void ldmx4t(uint32_t& b0, uint32_t& b1,
                                       uint32_t& b2, uint32_t& b3, uint32_t addr) {
    asm volatile("ldmatrix.sync.aligned.m8n8.x4.trans.shared.b16 {%0,%1,%2,%3}, [%4];"
                 : "=r"(b0), "=r"(b1), "=r"(b2), "=r"(b3) : "r"(addr));
}

__device__ __forceinline__ void cpa16(uint32_t dst, const void* src) {
    asm volatile("cp.async.cg.shared.global [%0], [%1], 16;" :: "r"(dst), "l"(src));
}
__device__ __forceinline__ void cpa_commit() {
    asm volatile("cp.async.commit_group;" ::: "memory");
}
template <int N>
__device__ __forceinline__ void cpa_wait() {
    asm volatile("cp.async.wait_group %0;" :: "n"(N) : "memory");
}

// ---------------------------------------------------------------------------
// GEMM body (R9-proven inner loop) — unchanged.
// ---------------------------------------------------------------------------
struct SmemGemm {
    uint32_t As[2][128][12];   // [buf][m][k2] packed half2 k-pairs
    uint32_t Bs[2][128][12];   // [buf][n][k2] (B transposed)
};

template <typename TOut>
__device__ __forceinline__ void gemm_body(
    SmemGemm& sm, const float* __restrict__ A, const float* __restrict__ B,
    TOut* __restrict__ C, int K, int NB, int NC, int m0, int bn0, int cn0) {

    const int tid = threadIdx.x;
    const int wid = tid >> 5;
    const int lane = tid & 31;
    const int g = lane >> 2;
    const int t = lane & 3;
    const int wm = (wid & 3) * 32;
    const int wn = (wid >> 2) * 64;

    const int aRow = tid >> 2;
    const int aK4  = (tid & 3) << 2;
    const int aK2  = (tid & 3) << 1;
    const int bN   = tid & 127;
    const int bKh  = tid >> 7;

    float acc[2][8][4];
#pragma unroll
    for (int mt = 0; mt < 2; ++mt)
#pragma unroll
        for (int nt = 0; nt < 8; ++nt)
#pragma unroll
            for (int r = 0; r < 4; ++r) acc[mt][nt][r] = 0.f;

    float4 ar[2];
    float  bv[4][2];

#pragma unroll
    for (int l = 0; l < 2; ++l)
        ar[l] = *(const float4*)(A + (size_t)(m0 + aRow + l * 64) * K + aK4);
#pragma unroll
    for (int l = 0; l < 4; ++l) {
        int k2 = bKh + 2 * l;
        bv[l][0] = B[(size_t)(2 * k2) * NB + bn0 + bN];
        bv[l][1] = B[(size_t)(2 * k2 + 1) * NB + bn0 + bN];
    }
#pragma unroll
    for (int l = 0; l < 2; ++l)
        *(uint2*)(&sm.As[0][aRow + l * 64][aK2]) =
            make_uint2(pack2h(ar[l].x, ar[l].y), pack2h(ar[l].z, ar[l].w));
#pragma unroll
    for (int l = 0; l < 4; ++l)
        sm.Bs[0][bN][bKh + 2 * l] = pack2h(bv[l][0], bv[l][1]);
    __syncthreads();

    const int KT = K >> 4;
    for (int kt = 0; kt < KT; ++kt) {
        const int buf = kt & 1;

        if (kt + 1 < KT) {
            const int k0n = (kt + 1) << 4;
#pragma unroll
            for (int l = 0; l < 2; ++l)
                ar[l] = *(const float4*)(A + (size_t)(m0 + aRow + l * 64) * K + k0n + aK4);
#pragma unroll
            for (int l = 0; l < 4; ++l) {
                int k2 = bKh + 2 * l;
                bv[l][0] = B[(size_t)(k0n + 2 * k2) * NB + bn0 + bN];
                bv[l][1] = B[(size_t)(k0n + 2 * k2 + 1) * NB + bn0 + bN];
            }
        }

        uint32_t af[2][4];
#pragma unroll
        for (int mt = 0; mt < 2; ++mt) {
            const int r0 = wm + mt * 16;
            af[mt][0] = sm.As[buf][r0 + g][t];
            af[mt][1] = sm.As[buf][r0 + g + 8][t];
            af[mt][2] = sm.As[buf][r0 + g][4 + t];
            af[mt][3] = sm.As[buf][r0 + g + 8][4 + t];
        }
#pragma unroll
        for (int nt = 0; nt < 8; ++nt) {
            const int n = wn + nt * 8 + g;
            uint32_t bf[2] = {sm.Bs[buf][n][t], sm.Bs[buf][n][4 + t]};
#pragma unroll
            for (int mt = 0; mt < 2; ++mt)
                mma_f16(acc[mt][nt], af[mt], bf, acc[mt][nt]);
        }

        if (kt + 1 < KT) {
            const int nb = buf ^ 1;
#pragma unroll
            for (int l = 0; l < 2; ++l)
                *(uint2*)(&sm.As[nb][aRow + l * 64][aK2]) =
                    make_uint2(pack2h(ar[l].x, ar[l].y), pack2h(ar[l].z, ar[l].w));
#pragma unroll
            for (int l = 0; l < 4; ++l)
                sm.Bs[nb][bN][bKh + 2 * l] = pack2h(bv[l][0], bv[l][1]);
            __syncthreads();
        }
    }

#pragma unroll
    for (int mt = 0; mt < 2; ++mt) {
        const int r0 = m0 + wm + mt * 16;
#pragma unroll
        for (int nt = 0; nt < 8; ++nt) {
            const int c0 = cn0 + wn + nt * 8 + t * 2;
            if (sizeof(TOut) == 4) {
                float* Cf = (float*)C;
                *(float2*)(Cf + (size_t)(r0 + g) * NC + c0) =
                    make_float2(acc[mt][nt][0], acc[mt][nt][1]);
                *(float2*)(Cf + (size_t)(r0 + g + 8) * NC + c0) =
                    make_float2(acc[mt][nt][2], acc[mt][nt][3]);
            } else {
                __half* Ch = (__half*)C;
                *(uint32_t*)(Ch + (size_t)(r0 + g) * NC + c0) =
                    pack2h(acc[mt][nt][0], acc[mt][nt][1]);
                *(uint32_t*)(Ch + (size_t)(r0 + g + 8) * NC + c0) =
                    pack2h(acc[mt][nt][2], acc[mt][nt][3]);
            }
        }
    }
}

template <typename TOut>
__global__ __launch_bounds__(256, 2)
void sgemm_f16(const float* __restrict__ A, const float* __restrict__ B,
               TOut* __restrict__ C, int M, int N, int K) {
    __shared__ SmemGemm sm;
    gemm_body<TOut>(sm, A, B, C, K, N, N, blockIdx.y * 128, blockIdx.x * 128,
                    blockIdx.x * 128);
}

__global__ __launch_bounds__(256, 2)
void sgemm_qkv(const float* __restrict__ x,
               const float* __restrict__ Wq, const float* __restrict__ Wk,
               const float* __restrict__ Wv,
               __half* __restrict__ q, __half* __restrict__ k,
               __half* __restrict__ v) {
    __shared__ SmemGemm sm;
    const int n0c = blockIdx.x * 128;
    const float* B;
    __half* C;
    int NB, n0;
    if (n0c < D_MODEL) {
        B = Wq; C = q; NB = D_MODEL; n0 = n0c;
    } else if (n0c < D_MODEL + KV_DIM) {
        B = Wk; C = k; NB = KV_DIM; n0 = n0c - D_MODEL;
    } else {
        B = Wv; C = v; NB = KV_DIM; n0 = n0c - D_MODEL - KV_DIM;
    }
    gemm_body<__half>(sm, x, B, C, D_MODEL, NB, NB, blockIdx.y * 128, n0, n0);
}

// ---------------------------------------------------------------------------
// RoPE in-place on fp16 [T, nheads, 128] buffers (rowstride in halves).
// ---------------------------------------------------------------------------
__global__ void rope_kernel_h(__half* __restrict__ buf, int nheads, int rowstride) {
    int idx = blockIdx.x * blockDim.x + threadIdx.x;
    int total = T_SEQ * nheads * 32;
    if (idx >= total) return;
    int i2 = idx & 31;
    int h = (idx >> 5) % nheads;
    int t = idx / (32 * nheads);

    float i0 = (float)(2 * i2);
    float i1 = (float)(2 * i2 + 1);
    float inv0 = powf(10000.f, -i0 / (float)HALF);
    float inv1 = powf(10000.f, -i1 / (float)HALF);
    float s0, c0, s1, c1;
    sincosf((float)t * inv0, &s0, &c0);
    sincosf((float)t * inv1, &s1, &c1);

    __half* base = buf + (size_t)t * rowstride + h * DH;
    float2 x1 = __half22float2(*(__half2*)(base + 2 * i2));
    float2 x2 = __half22float2(*(__half2*)(base + HALF + 2 * i2));
    *(__half2*)(base + 2 * i2) =
        __floats2half2_rn(x1.x * c0 - x2.x * s0, x1.y * c1 - x2.y * s1);
    *(__half2*)(base + HALF + 2 * i2) =
        __floats2half2_rn(x1.x * s0 + x2.x * c0, x1.y * s1 + x2.y * c1);
}

// ---------------------------------------------------------------------------
// Flash attention v7: 256 threads / 8 warps over 128 query rows x 1 head.
// Same per-warp mma/softmax code as v6; K/V cp.async double-buffered, one
// 64-key staging now feeds 8 warps; heavy-blocks-first scheduling.
// Smem (u32): Qh[128][68]=8704, K0/K1[64][68], V0/V1[64][68].
// ---------------------------------------------------------------------------
#define AOQ  0
#define AOK0 8704
#define AOK1 13056
#define AOV0 17408
#define AOV1 21760
#define ATTN_SMEM_BYTES (26112 * 4)   // 104448

__global__ __launch_bounds__(256, 2)
void attn_kernel(const __half* __restrict__ q, const __half* __restrict__ k,
                 const __half* __restrict__ v, float* __restrict__ y) {
    extern __shared__ uint32_t smu[];
    uint32_t* Qh = smu + AOQ;

    const int qb = (gridDim.x - 1) - blockIdx.x;   // heavy blocks first
    const int hq = blockIdx.y;
    const int hkv = hq >> 2;
    const int q0 = qb * 128;
    const int tid = threadIdx.x;
    const int wid = tid >> 5;                      // 0..7
    const int lane = tid & 31;
    const int g = lane >> 2;
    const int t = lane & 3;
    const int r0 = wid * 16;                       // warp's q-row group (0..112)
    const int rg0 = q0 + r0 + g;
    const int rg1 = rg0 + 8;

    // staging chunk indices (4 K + 4 V chunks of 16B per thread)
    const int sRow = tid >> 4;              // base row 0..15 (+16 per l)
    const int sD16 = tid & 15;              // 16B chunk within 256B row

    const uint32_t kBase[2] = {smem_u32(smu + AOK0), smem_u32(smu + AOK1)};
    const uint32_t vBase[2] = {smem_u32(smu + AOV0), smem_u32(smu + AOV1)};

    // ---- stage Q once (pure uint4 copy: 128 rows x 16 uint4)
#pragma unroll
    for (int l = 0; l < 8; ++l) {
        int lin = tid + l * 256;
        int row = lin >> 4;
        int d8 = lin & 15;
        uint4 u = *(const uint4*)(q + (size_t)(q0 + row) * D_MODEL + hq * DH + d8 * 8);
        *(uint4*)(Qh + row * 68 + d8 * 4) = u;
    }

    // ---- issue async K/V for block 0 into buffer 0
    {
        const __half* kp = k + hkv * DH;
        const __half* vp = v + hkv * DH;
#pragma unroll
        for (int l = 0; l < 4; ++l) {
            int row = sRow + l * 16;
            cpa16(kBase[0] + row * 272 + sD16 * 16,
                  kp + (size_t)row * KV_DIM + sD16 * 8);
            cpa16(vBase[0] + row * 272 + sD16 * 16,
                  vp + (size_t)row * KV_DIM + sD16 * 8);
        }
        cpa_commit();
    }

    float acc[16][4];
#pragma unroll
    for (int n = 0; n < 16; ++n)
#pragma unroll
        for (int r = 0; r < 4; ++r) acc[n][r] = 0.f;
    float m_i[2] = {-1e30f, -1e30f};
    float l_i[2] = {0.f, 0.f};

    const float scale = 0.08838834764831845f;   // 1/sqrt(128)

    const int nkb = 2 * qb + 2;
    for (int jb = 0; jb < nkb; ++jb) {
        const int j0 = jb * 64;
        const int buf = jb & 1;
        __syncthreads();   // previous compute done before its buffer is overwritten

        // ---- issue async K/V for block jb+1 into the other buffer
        if (jb + 1 < nkb) {
            const int jn = (jb + 1) * 64;
            const int nb = buf ^ 1;
            const __half* kp = k + (size_t)jn * KV_DIM + hkv * DH;
            const __half* vp = v + (size_t)jn * KV_DIM + hkv * DH;
#pragma unroll
            for (int l = 0; l < 4; ++l) {
                int row = sRow + l * 16;
                cpa16(kBase[nb] + row * 272 + sD16 * 16,
                      kp + (size_t)row * KV_DIM + sD16 * 8);
                cpa16(vBase[nb] + row * 272 + sD16 * 16,
                      vp + (size_t)row * KV_DIM + sD16 * 8);
            }
            cpa_commit();
            cpa_wait<1>();   // block jb's group complete
        } else {
            cpa_wait<0>();
        }
        __syncthreads();     // completed copies visible to all warps

        if (j0 > q0 + r0 + 15) continue;   // warp fully above this key block

        const uint32_t* Kh = smu + (buf ? AOK1 : AOK0);
        const __half*   Vh = (const __half*)(smu + (buf ? AOV1 : AOV0));

        // ---- S = Q K^T
        float sf[8][4];
#pragma unroll
        for (int nt = 0; nt < 8; ++nt)
#pragma unroll
            for (int r = 0; r < 4; ++r) sf[nt][r] = 0.f;

        const uint32_t* qr0 = Qh + (r0 + g) * 68;
        const uint32_t* qr1 = Qh + (r0 + g + 8) * 68;
#pragma unroll
        for (int ks = 0; ks < 8; ++ks) {
            const int kk = ks * 8;
            uint32_t a[4] = {qr0[kk + t], qr1[kk + t], qr0[kk + 4 + t], qr1[kk + 4 + t]};
#pragma unroll
            for (int nt = 0; nt < 8; ++nt) {
                const uint32_t* kr = Kh + (nt * 8 + g) * 68 + kk;
                uint32_t b[2] = {kr[t], kr[4 + t]};
                mma_f16(sf[nt], a, b, sf[nt]);
            }
        }

        // ---- scale + causal mask
#pragma unroll
        for (int nt = 0; nt < 8; ++nt) {
            sf[nt][0] *= scale; sf[nt][1] *= scale;
            sf[nt][2] *= scale; sf[nt][3] *= scale;
        }
        if (j0 + 63 > rg0) {
#pragma unroll
            for (int nt = 0; nt < 8; ++nt) {
                const int c = j0 + nt * 8 + 2 * t;
                if (c     > rg0) sf[nt][0] = -1e30f;
                if (c + 1 > rg0) sf[nt][1] = -1e30f;
                if (c     > rg1) sf[nt][2] = -1e30f;
                if (c + 1 > rg1) sf[nt][3] = -1e30f;
            }
        }

        // ---- online softmax (quad-local)
        float mx0 = -1e30f, mx1 = -1e30f;
#pragma unroll
        for (int nt = 0; nt < 8; ++nt) {
            mx0 = fmaxf(mx0, fmaxf(sf[nt][0], sf[nt][1]));
            mx1 = fmaxf(mx1, fmaxf(sf[nt][2], sf[nt][3]));
        }
        mx0 = fmaxf(mx0, __shfl_xor_sync(0xffffffffu, mx0, 1));
        mx0 = fmaxf(mx0, __shfl_xor_sync(0xffffffffu, mx0, 2));
        mx1 = fmaxf(mx1, __shfl_xor_sync(0xffffffffu, mx1, 1));
        mx1 = fmaxf(mx1, __shfl_xor_sync(0xffffffffu, mx1, 2));

        const float mn0 = fmaxf(m_i[0], mx0);
        const float mn1 = fmaxf(m_i[1], mx1);
        const float al0 = __expf(m_i[0] - mn0);
        const float al1 = __expf(m_i[1] - mn1);

        float sum0 = 0.f, sum1 = 0.f;
#pragma unroll
        for (int nt = 0; nt < 8; ++nt) {
            sf[nt][0] = __expf(sf[nt][0] - mn0);
            sf[nt][1] = __expf(sf[nt][1] - mn0);
            sf[nt][2] = __expf(sf[nt][2] - mn1);
            sf[nt][3] = __expf(sf[nt][3] - mn1);
            sum0 += sf[nt][0] + sf[nt][1];
            sum1 += sf[nt][2] + sf[nt][3];
        }
        sum0 += __shfl_xor_sync(0xffffffffu, sum0, 1);
        sum0 += __shfl_xor_sync(0xffffffffu, sum0, 2);
        sum1 += __shfl_xor_sync(0xffffffffu, sum1, 1);
        sum1 += __shfl_xor_sync(0xffffffffu, sum1, 2);

        l_i[0] = l_i[0] * al0 + sum0;
        l_i[1] = l_i[1] * al1 + sum1;
        m_i[0] = mn0;
        m_i[1] = mn1;

#pragma unroll
        for (int n = 0; n < 16; ++n) {
            acc[n][0] *= al0; acc[n][1] *= al0;
            acc[n][2] *= al1; acc[n][3] *= al1;
        }

        // ---- O += P V
        const int vrow = lane & 15;
        const int vcol8 = (lane >> 4) * 8;
#pragma unroll
        for (int ks = 0; ks < 4; ++ks) {
            uint32_t a[4] = {pack2h(sf[2 * ks][0],     sf[2 * ks][1]),
                             pack2h(sf[2 * ks][2],     sf[2 * ks][3]),
                             pack2h(sf[2 * ks + 1][0], sf[2 * ks + 1][1]),
                             pack2h(sf[2 * ks + 1][2], sf[2 * ks + 1][3])};
            const __half* vbase = Vh + (16 * ks + vrow) * 136 + vcol8;
#pragma unroll
            for (int ntp = 0; ntp < 8; ++ntp) {
                uint32_t b0, b1, b2, b3;
                ldmx4t(b0, b1, b2, b3, smem_u32(vbase + ntp * 16));
                uint32_t blo[2] = {b0, b1};
                uint32_t bhi[2] = {b2, b3};
                mma_f16(acc[2 * ntp],     a, blo, acc[2 * ntp]);
                mma_f16(acc[2 * ntp + 1], a, bhi, acc[2 * ntp + 1]);
            }
        }
    }

    // ---- normalize + write
    const float i0 = 1.f / l_i[0];
    const float i1 = 1.f / l_i[1];
    float* y0 = y + (size_t)rg0 * D_MODEL + hq * DH;
    float* y1 = y + (size_t)rg1 * D_MODEL + hq * DH;
#pragma unroll
    for (int n = 0; n < 16; ++n) {
        const int c0 = n * 8 + 2 * t;
        *(float2*)(y0 + c0) = make_float2(acc[n][0] * i0, acc[n][1] * i0);
        *(float2*)(y1 + c0) = make_float2(acc[n][2] * i1, acc[n][3] * i1);
    }
}

// ---------------------------------------------------------------------------
extern "C" void kernel_launch(void* const* d_in, const int* in_sizes, int n_in,
                              void* d_out, int out_size) {
    const float* x  = (const float*)d_in[0];
    const float* Wq = (const float*)d_in[1];
    const float* Wk = (const float*)d_in[2];
    const float* Wv = (const float*)d_in[3];
    const float* Wo = (const float*)d_in[4];
    float* out = (float*)d_out;

    void *pq, *pk, *pv, *py;
    cudaGetSymbolAddress(&pq, g_qh);
    cudaGetSymbolAddress(&pk, g_kh);
    cudaGetSymbolAddress(&pv, g_vh);
    cudaGetSymbolAddress(&py, g_y);
    __half* qh = (__half*)pq;
    __half* kh = (__half*)pk;
    __half* vh = (__half*)pv;
    float*  y  = (float*)py;

    // Fused Q/K/V projections: one launch, 768 CTAs
    sgemm_qkv<<<dim3((D_MODEL + 2 * KV_DIM) / 128, T_SEQ / 128), 256>>>(
        x, Wq, Wk, Wv, qh, kh, vh);

    // RoPE on fp16 buffers
    {
        int nq = T_SEQ * N_HEADS * 32;
        rope_kernel_h<<<(nq + 255) / 256, 256>>>(qh, N_HEADS, D_MODEL);
        int nk = T_SEQ * N_KV * 32;
        rope_kernel_h<<<(nk + 255) / 256, 256>>>(kh, N_KV, KV_DIM);
    }

    // Attention (256-thread CTAs over 128 q rows, cp.async double-buffered)
    cudaFuncSetAttribute(attn_kernel, cudaFuncAttributeMaxDynamicSharedMemorySize, ATTN_SMEM_BYTES);
    attn_kernel<<<dim3(T_SEQ / 128, N_HEADS), 256, ATTN_SMEM_BYTES>>>(qh, kh, vh, y);

    // Output projection (fp32 output)
    sgemm_f16<float><<<dim3(D_MODEL / 128, T_SEQ / 128), 256>>>(y, Wo, out, T_SEQ, D_MODEL, D_MODEL);
}

// round 15
// speedup vs baseline: 1.1704x; 1.0049x over previous
#include <cuda_runtime.h>
#include <cuda_fp16.h>
#include <math.h>
#include <cstdint>

// Problem constants
#define T_SEQ 4096
#define D_MODEL 2048
#define N_HEADS 16
#define N_KV 4
#define DH 128
#define HALF 64
#define KV_DIM 512   // N_KV * DH
#define QKV_N (D_MODEL + 2 * KV_DIM)   // 3072

// Scratch (device globals; no allocation allowed)
__device__ __half g_xh[T_SEQ * D_MODEL];          // x as fp16
__device__ __half g_wqkvt[QKV_N * D_MODEL];       // [Wq;Wk;Wv]^T as fp16 [n][k]
__device__ __half g_wot[D_MODEL * D_MODEL];       // Wo^T as fp16 [n][k]
__device__ __half g_qh[T_SEQ * D_MODEL];
__device__ __half g_kh[T_SEQ * KV_DIM];
__device__ __half g_vh[T_SEQ * KV_DIM];
__device__ __half g_yh[T_SEQ * D_MODEL];          // attention output, fp16

// ---------------------------------------------------------------------------
// helpers
// ---------------------------------------------------------------------------
__device__ __forceinline__ uint32_t pack2h(float lo, float hi) {
    __half2 h = __floats2half2_rn(lo, hi);   // .x = lo -> low 16 bits
    return *(uint32_t*)&h;
}

__device__ __forceinline__ void mma_f16(float* d, const uint32_t* a,
                                        const uint32_t* b, const float* c) {
    asm volatile(
        "mma.sync.aligned.m16n8k16.row.col.f32.f16.f16.f32 "
        "{%0,%1,%2,%3}, {%4,%5,%6,%7}, {%8,%9}, {%10,%11,%12,%13};"
        : "=f"(d[0]), "=f"(d[1]), "=f"(d[2]), "=f"(d[3])
        : "r"(a[0]), "r"(a[1]), "r"(a[2]), "r"(a[3]),
          "r"(b[0]), "r"(b[1]),
          "f"(c[0]), "f"(c[1]), "f"(c[2]), "f"(c[3]));
}

__device__ __forceinline__ uint32_t smem_u32(const void* p) {
    uint32_t a;
    asm("{ .reg .u64 t; cvta.to.shared.u64 t, %1; cvt.u32.u64 %0, t; }" : "=r"(a) : "l"(p));
    return a;
}

__device__ __forceinline__ void ldmx4t(uint32_t& b0, uint32_t& b1,
                                       uint32_t& b2, uint32_t& b3, uint32_t addr) {
    asm volatile("ldmatrix.sync.aligned.m8n8.x4.trans.shared.b16 {%0,%1,%2,%3}, [%4];"
                 : "=r"(b0), "=r"(b1), "=r"(b2), "=r"(b3) : "r"(addr));
}

__device__ __forceinline__ void cpa16(uint32_t dst, const void* src) {
    asm volatile("cp.async.cg.shared.global [%0], [%1], 16;" :: "r"(dst), "l"(src));
}
__device__ __forceinline__ void cpa_commit() {
    asm volatile("cp.async.commit_group;" ::: "memory");
}
template <int N>
__device__ __forceinline__ void cpa_wait() {
    asm volatile("cp.async.wait_group %0;" :: "n"(N) : "memory");
}

// ---------------------------------------------------------------------------
// One-time operand preparation
// ---------------------------------------------------------------------------
// fp32 -> fp16, 8 elements per thread (n must be a multiple of 8)
__global__ void cvt_f32_f16(const float* __restrict__ in, __half* __restrict__ out) {
    int i = (blockIdx.x * blockDim.x + threadIdx.x) * 8;
    float4 a = *(const float4*)(in + i);
    float4 b = *(const float4*)(in + i + 4);
    uint4 u;
    u.x = pack2h(a.x, a.y); u.y = pack2h(a.z, a.w);
    u.z = pack2h(b.x, b.y); u.w = pack2h(b.z, b.w);
    *(uint4*)(out + i) = u;
}

// W[K][N] fp32 -> Wt[N][K] fp16  (32x32 smem tile, 32x8 threads)
__global__ void transpose_f32_f16(const float* __restrict__ W,
                                  __half* __restrict__ Wt, int K, int N) {
    __shared__ float tile[32][33];
    const int k0 = blockIdx.y * 32;
    const int n0 = blockIdx.x * 32;
#pragma unroll
    for (int i = threadIdx.y; i < 32; i += 8)
        tile[i][threadIdx.x] = W[(size_t)(k0 + i) * N + n0 + threadIdx.x];
    __syncthreads();
#pragma unroll
    for (int i = threadIdx.y; i < 32; i += 8)
        Wt[(size_t)(n0 + i) * K + k0 + threadIdx.x] = __float2half(tile[threadIdx.x][i]);
}

// ---------------------------------------------------------------------------
// FP16 GEMM with pure-copy staging: A[M][K] fp16 row-major, Bt[N][K] fp16
// (k-major), C fp16 or fp32. CTA 128x128, BK=16, 256 threads, 8 warps.
// Inner fragment/mma code identical to the proven R9 loop.
// ---------------------------------------------------------------------------
struct SmemH {
    uint32_t As[2][128][12];   // [buf][m][k2], 8 used + 4 pad
    uint32_t Bs[2][128][12];   // [buf][n][k2]
};

template <typename TOut>
__device__ __forceinline__ void hgemm_body(
    SmemH& sm, const __half* __restrict__ A, const __half* __restrict__ Bt,
    TOut* __restrict__ C, int K, int NC, int m0, int nb0, int cn0) {

    const int tid = threadIdx.x;
    const int wid = tid >> 5;
    const int lane = tid & 31;
    const int g = lane >> 2;
    const int t = lane & 3;
    const int wm = (wid & 3) * 32;
    const int wn = (wid >> 2) * 64;

    const int sRow = tid >> 1;         // 0..127
    const int sCh  = (tid & 1) * 4;    // u32 col 0 or 4 (8 halves)

    float acc[2][8][4];
#pragma unroll
    for (int mt = 0; mt < 2; ++mt)
#pragma unroll
        for (int nt = 0; nt < 8; ++nt)
#pragma unroll
            for (int r = 0; r < 4; ++r) acc[mt][nt][r] = 0.f;

    // prologue: tile 0 (pure copies)
    uint4 av = *(const uint4*)(A + (size_t)(m0 + sRow) * K + sCh * 2);
    uint4 bv = *(const uint4*)(Bt + (size_t)(nb0 + sRow) * K + sCh * 2);
    *(uint4*)(&sm.As[0][sRow][sCh]) = av;
    *(uint4*)(&sm.Bs[0][sRow][sCh]) = bv;
    __syncthreads();

    const int KT = K >> 4;
    for (int kt = 0; kt < KT; ++kt) {
        const int buf = kt & 1;

        // prefetch tile kt+1
        if (kt + 1 < KT) {
            const int k0n = (kt + 1) << 4;
            av = *(const uint4*)(A + (size_t)(m0 + sRow) * K + k0n + sCh * 2);
            bv = *(const uint4*)(Bt + (size_t)(nb0 + sRow) * K + k0n + sCh * 2);
        }

        // compute tile kt (identical fragment/mma pattern)
        uint32_t af[2][4];
#pragma unroll
        for (int mt = 0; mt < 2; ++mt) {
            const int r0 = wm + mt * 16;
            af[mt][0] = sm.As[buf][r0 + g][t];
            af[mt][1] = sm.As[buf][r0 + g + 8][t];
            af[mt][2] = sm.As[buf][r0 + g][4 + t];
            af[mt][3] = sm.As[buf][r0 + g + 8][4 + t];
        }
#pragma unroll
        for (int nt = 0; nt < 8; ++nt) {
            const int n = wn + nt * 8 + g;
            uint32_t bf[2] = {sm.Bs[buf][n][t], sm.Bs[buf][n][4 + t]};
#pragma unroll
            for (int mt = 0; mt < 2; ++mt)
                mma_f16(acc[mt][nt], af[mt], bf, acc[mt][nt]);
        }

        // stage tile kt+1
        if (kt + 1 < KT) {
            const int nb = buf ^ 1;
            *(uint4*)(&sm.As[nb][sRow][sCh]) = av;
            *(uint4*)(&sm.Bs[nb][sRow][sCh]) = bv;
            __syncthreads();
        }
    }

    // epilogue
#pragma unroll
    for (int mt = 0; mt < 2; ++mt) {
        const int r0 = m0 + wm + mt * 16;
#pragma unroll
        for (int nt = 0; nt < 8; ++nt) {
            const int c0 = cn0 + wn + nt * 8 + t * 2;
            if (sizeof(TOut) == 4) {
                float* Cf = (float*)C;
                *(float2*)(Cf + (size_t)(r0 + g) * NC + c0) =
                    make_float2(acc[mt][nt][0], acc[mt][nt][1]);
                *(float2*)(Cf + (size_t)(r0 + g + 8) * NC + c0) =
                    make_float2(acc[mt][nt][2], acc[mt][nt][3]);
            } else {
                __half* Ch = (__half*)C;
                *(uint32_t*)(Ch + (size_t)(r0 + g) * NC + c0) =
                    pack2h(acc[mt][nt][0], acc[mt][nt][1]);
                *(uint32_t*)(Ch + (size_t)(r0 + g + 8) * NC + c0) =
                    pack2h(acc[mt][nt][2], acc[mt][nt][3]);
            }
        }
    }
}

// Fused Q/K/V projection over the concatenated transposed weights.
__global__ __launch_bounds__(256, 2)
void hgemm_qkv(const __half* __restrict__ xh, const __half* __restrict__ Wqkvt,
               __half* __restrict__ q, __half* __restrict__ k,
               __half* __restrict__ v) {
    __shared__ SmemH sm;
    const int n0c = blockIdx.x * 128;
    __half* C;
    int NC, cn0;
    if (n0c < D_MODEL)                { C = q; NC = D_MODEL; cn0 = n0c; }
    else if (n0c < D_MODEL + KV_DIM)  { C = k; NC = KV_DIM;  cn0 = n0c - D_MODEL; }
    else                              { C = v; NC = KV_DIM;  cn0 = n0c - D_MODEL - KV_DIM; }
    hgemm_body<__half>(sm, xh, Wqkvt, C, D_MODEL, NC, blockIdx.y * 128, n0c, cn0);
}

// Output projection: A = yh fp16, Bt = Wot fp16, C = out fp32.
__global__ __launch_bounds__(256, 2)
void hgemm_out(const __half* __restrict__ yh, const __half* __restrict__ Wot,
               float* __restrict__ out) {
    __shared__ SmemH sm;
    hgemm_body<float>(sm, yh, Wot, out, D_MODEL, D_MODEL, blockIdx.y * 128,
                      blockIdx.x * 128, blockIdx.x * 128);
}

// ---------------------------------------------------------------------------
// RoPE in-place on fp16 [T, nheads, 128] buffers (rowstride in halves).
// ---------------------------------------------------------------------------
__global__ void rope_kernel_h(__half* __restrict__ buf, int nheads, int rowstride) {
    int idx = blockIdx.x * blockDim.x + threadIdx.x;
    int total = T_SEQ * nheads * 32;
    if (idx >= total) return;
    int i2 = idx & 31;
    int h = (idx >> 5) % nheads;
    int t = idx / (32 * nheads);

    float i0 = (float)(2 * i2);
    float i1 = (float)(2 * i2 + 1);
    float inv0 = powf(10000.f, -i0 / (float)HALF);
    float inv1 = powf(10000.f, -i1 / (float)HALF);
    float s0, c0, s1, c1;
    sincosf((float)t * inv0, &s0, &c0);
    sincosf((float)t * inv1, &s1, &c1);

    __half* base = buf + (size_t)t * rowstride + h * DH;
    float2 x1 = __half22float2(*(__half2*)(base + 2 * i2));
    float2 x2 = __half22float2(*(__half2*)(base + HALF + 2 * i2));
    *(__half2*)(base + 2 * i2) =
        __floats2half2_rn(x1.x * c0 - x2.x * s0, x1.y * c1 - x2.y * s1);
    *(__half2*)(base + HALF + 2 * i2) =
        __floats2half2_rn(x1.x * s0 + x2.x * c0, x1.y * s1 + x2.y * c1);
}

// ---------------------------------------------------------------------------
// Flash attention v7 (unchanged from R14) except: writes y as fp16.
// 256 threads / 8 warps over 128 q rows; cp.async double-buffered K/V.
// ---------------------------------------------------------------------------
#define AOQ  0
#define AOK0 8704
#define AOK1 13056
#define AOV0 17408
#define AOV1 21760
#define ATTN_SMEM_BYTES (26112 * 4)   // 104448

__global__ __launch_bounds__(256, 2)
void attn_kernel(const __half* __restrict__ q, const __half* __restrict__ k,
                 const __half* __restrict__ v, __half* __restrict__ y) {
    extern __shared__ uint32_t smu[];
    uint32_t* Qh = smu + AOQ;

    const int qb = (gridDim.x - 1) - blockIdx.x;   // heavy blocks first
    const int hq = blockIdx.y;
    const int hkv = hq >> 2;
    const int q0 = qb * 128;
    const int tid = threadIdx.x;
    const int wid = tid >> 5;
    const int lane = tid & 31;
    const int g = lane >> 2;
    const int t = lane & 3;
    const int r0 = wid * 16;
    const int rg0 = q0 + r0 + g;
    const int rg1 = rg0 + 8;

    const int sRow = tid >> 4;
    const int sD16 = tid & 15;

    const uint32_t kBase[2] = {smem_u32(smu + AOK0), smem_u32(smu + AOK1)};
    const uint32_t vBase[2] = {smem_u32(smu + AOV0), smem_u32(smu + AOV1)};

    // stage Q once
#pragma unroll
    for (int l = 0; l < 8; ++l) {
        int lin = tid + l * 256;
        int row = lin >> 4;
        int d8 = lin & 15;
        uint4 u = *(const uint4*)(q + (size_t)(q0 + row) * D_MODEL + hq * DH + d8 * 8);
        *(uint4*)(Qh + row * 68 + d8 * 4) = u;
    }

    // async K/V block 0 -> buffer 0
    {
        const __half* kp = k + hkv * DH;
        const __half* vp = v + hkv * DH;
#pragma unroll
        for (int l = 0; l < 4; ++l) {
            int row = sRow + l * 16;
            cpa16(kBase[0] + row * 272 + sD16 * 16, kp + (size_t)row * KV_DIM + sD16 * 8);
            cpa16(vBase[0] + row * 272 + sD16 * 16, vp + (size_t)row * KV_DIM + sD16 * 8);
        }
        cpa_commit();
    }

    float acc[16][4];
#pragma unroll
    for (int n = 0; n < 16; ++n)
#pragma unroll
        for (int r = 0; r < 4; ++r) acc[n][r] = 0.f;
    float m_i[2] = {-1e30f, -1e30f};
    float l_i[2] = {0.f, 0.f};

    const float scale = 0.08838834764831845f;   // 1/sqrt(128)

    const int nkb = 2 * qb + 2;
    for (int jb = 0; jb < nkb; ++jb) {
        const int j0 = jb * 64;
        const int buf = jb & 1;
        __syncthreads();

        if (jb + 1 < nkb) {
            const int jn = (jb + 1) * 64;
            const int nb = buf ^ 1;
            const __half* kp = k + (size_t)jn * KV_DIM + hkv * DH;
            const __half* vp = v + (size_t)jn * KV_DIM + hkv * DH;
#pragma unroll
            for (int l = 0; l < 4; ++l) {
                int row = sRow + l * 16;
                cpa16(kBase[nb] + row * 272 + sD16 * 16, kp + (size_t)row * KV_DIM + sD16 * 8);
                cpa16(vBase[nb] + row * 272 + sD16 * 16, vp + (size_t)row * KV_DIM + sD16 * 8);
            }
            cpa_commit();
            cpa_wait<1>();
        } else {
            cpa_wait<0>();
        }
        __syncthreads();

        if (j0 > q0 + r0 + 15) continue;

        const uint32_t* Kh = smu + (buf ? AOK1 : AOK0);
        const __half*   Vh = (const __half*)(smu + (buf ? AOV1 : AOV0));

        // S = Q K^T
        float sf[8][4];
#pragma unroll
        for (int nt = 0; nt < 8; ++nt)
#pragma unroll
            for (int r = 0; r < 4; ++r) sf[nt][r] = 0.f;

        const uint32_t* qr0 = Qh + (r0 + g) * 68;
        const uint32_t* qr1 = Qh + (r0 + g + 8) * 68;
#pragma unroll
        for (int ks = 0; ks < 8; ++ks) {
            const int kk = ks * 8;
            uint32_t a[4] = {qr0[kk + t], qr1[kk + t], qr0[kk + 4 + t], qr1[kk + 4 + t]};
#pragma unroll
            for (int nt = 0; nt < 8; ++nt) {
                const uint32_t* kr = Kh + (nt * 8 + g) * 68 + kk;
                uint32_t b[2] = {kr[t], kr[4 + t]};
                mma_f16(sf[nt], a, b, sf[nt]);
            }
        }

        // scale + causal mask
#pragma unroll
        for (int nt = 0; nt < 8; ++nt) {
            sf[nt][0] *= scale; sf[nt][1] *= scale;
            sf[nt][2] *= scale; sf[nt][3] *= scale;
        }
        if (j0 + 63 > rg0) {
#pragma unroll
            for (int nt = 0; nt < 8; ++nt) {
                const int c = j0 + nt * 8 + 2 * t;
                if (c     > rg0) sf[nt][0] = -1e30f;
                if (c + 1 > rg0) sf[nt][1] = -1e30f;
                if (c     > rg1) sf[nt][2] = -1e30f;
                if (c + 1 > rg1) sf[nt][3] = -1e30f;
            }
        }

        // online softmax (quad-local)
        float mx0 = -1e30f, mx1 = -1e30f;
#pragma unroll
        for (int nt = 0; nt < 8; ++nt) {
            mx0 = fmaxf(mx0, fmaxf(sf[nt][0], sf[nt][1]));
            mx1 = fmaxf(mx1, fmaxf(sf[nt][2], sf[nt][3]));
        }
        mx0 = fmaxf(mx0, __shfl_xor_sync(0xffffffffu, mx0, 1));
        mx0 = fmaxf(mx0, __shfl_xor_sync(0xffffffffu, mx0, 2));
        mx1 = fmaxf(mx1, __shfl_xor_sync(0xffffffffu, mx1, 1));
        mx1 = fmaxf(mx1, __shfl_xor_sync(0xffffffffu, mx1, 2));

        const float mn0 = fmaxf(m_i[0], mx0);
        const float mn1 = fmaxf(m_i[1], mx1);
        const float al0 = __expf(m_i[0] - mn0);
        const float al1 = __expf(m_i[1] - mn1);

        float sum0 = 0.f, sum1 = 0.f;
#pragma unroll
        for (int nt = 0; nt < 8; ++nt) {
            sf[nt][0] = __expf(sf[nt][0] - mn0);
            sf[nt][1] = __expf(sf[nt][1] - mn0);
            sf[nt][2] = __expf(sf[nt][2] - mn1);
            sf[nt][3] = __expf(sf[nt][3] - mn1);
            sum0 += sf[nt][0] + sf[nt][1];
            sum1 += sf[nt][2] + sf[nt][3];
        }
        sum0 += __shfl_xor_sync(0xffffffffu, sum0, 1);
        sum0 += __shfl_xor_sync(0xffffffffu, sum0, 2);
        sum1 += __shfl_xor_sync(0xffffffffu, sum1, 1);
        sum1 += __shfl_xor_sync(0xffffffffu, sum1, 2);

        l_i[0] = l_i[0] * al0 + sum0;
        l_i[1] = l_i[1] * al1 + sum1;
        m_i[0] = mn0;
        m_i[1] = mn1;

#pragma unroll
        for (int n = 0; n < 16; ++n) {
            acc[n][0] *= al0; acc[n][1] *= al0;
            acc[n][2] *= al1; acc[n][3] *= al1;
        }

        // O += P V
        const int vrow = lane & 15;
        const int vcol8 = (lane >> 4) * 8;
#pragma unroll
        for (int ks = 0; ks < 4; ++ks) {
            uint32_t a[4] = {pack2h(sf[2 * ks][0],     sf[2 * ks][1]),
                             pack2h(sf[2 * ks][2],     sf[2 * ks][3]),
                             pack2h(sf[2 * ks + 1][0], sf[2 * ks + 1][1]),
                             pack2h(sf[2 * ks + 1][2], sf[2 * ks + 1][3])};
            const __half* vbase = Vh + (16 * ks + vrow) * 136 + vcol8;
#pragma unroll
            for (int ntp = 0; ntp < 8; ++ntp) {
                uint32_t b0, b1, b2, b3;
                ldmx4t(b0, b1, b2, b3, smem_u32(vbase + ntp * 16));
                uint32_t blo[2] = {b0, b1};
                uint32_t bhi[2] = {b2, b3};
                mma_f16(acc[2 * ntp],     a, blo, acc[2 * ntp]);
                mma_f16(acc[2 * ntp + 1], a, bhi, acc[2 * ntp + 1]);
            }
        }
    }

    // normalize + write y as fp16 (same rounding the out-proj staging used)
    const float i0 = 1.f / l_i[0];
    const float i1 = 1.f / l_i[1];
    __half* y0 = y + (size_t)rg0 * D_MODEL + hq * DH;
    __half* y1 = y + (size_t)rg1 * D_MODEL + hq * DH;
#pragma unroll
    for (int n = 0; n < 16; ++n) {
        const int c0 = n * 8 + 2 * t;
        *(uint32_t*)(y0 + c0) = pack2h(acc[n][0] * i0, acc[n][1] * i0);
        *(uint32_t*)(y1 + c0) = pack2h(acc[n][2] * i1, acc[n][3] * i1);
    }
}

// ---------------------------------------------------------------------------
extern "C" void kernel_launch(void* const* d_in, const int* in_sizes, int n_in,
                              void* d_out, int out_size) {
    const float* x  = (const float*)d_in[0];
    const float* Wq = (const float*)d_in[1];
    const float* Wk = (const float*)d_in[2];
    const float* Wv = (const float*)d_in[3];
    const float* Wo = (const float*)d_in[4];
    float* out = (float*)d_out;

    void *pxh, *pwqkvt, *pwot, *pq, *pk, *pv, *py;
    cudaGetSymbolAddress(&pxh, g_xh);
    cudaGetSymbolAddress(&pwqkvt, g_wqkvt);
    cudaGetSymbolAddress(&pwot, g_wot);
    cudaGetSymbolAddress(&pq, g_qh);
    cudaGetSymbolAddress(&pk, g_kh);
    cudaGetSymbolAddress(&pv, g_vh);
    cudaGetSymbolAddress(&py, g_yh);
    __half* xh    = (__half*)pxh;
    __half* wqkvt = (__half*)pwqkvt;
    __half* wot   = (__half*)pwot;
    __half* qh    = (__half*)pq;
    __half* kh    = (__half*)pk;
    __half* vh    = (__half*)pv;
    __half* yh    = (__half*)py;

    // ---- one-time operand prep (same rounding as previous in-loop cvt)
    cvt_f32_f16<<<(T_SEQ * D_MODEL) / (256 * 8), 256>>>(x, xh);
    {
        dim3 thr(32, 8);
        transpose_f32_f16<<<dim3(D_MODEL / 32, D_MODEL / 32), thr>>>(Wq, wqkvt, D_MODEL, D_MODEL);
        transpose_f32_f16<<<dim3(KV_DIM / 32, D_MODEL / 32), thr>>>(
            Wk, wqkvt + (size_t)D_MODEL * D_MODEL, D_MODEL, KV_DIM);
        transpose_f32_f16<<<dim3(KV_DIM / 32, D_MODEL / 32), thr>>>(
            Wv, wqkvt + (size_t)(D_MODEL + KV_DIM) * D_MODEL, D_MODEL, KV_DIM);
        transpose_f32_f16<<<dim3(D_MODEL / 32, D_MODEL / 32), thr>>>(Wo, wot, D_MODEL, D_MODEL);
    }

    // ---- fused Q/K/V projection (pure-copy staging)
    hgemm_qkv<<<dim3(QKV_N / 128, T_SEQ / 128), 256>>>(xh, wqkvt, qh, kh, vh);

    // ---- RoPE on fp16 buffers
    {
        int nq = T_SEQ * N_HEADS * 32;
        rope_kernel_h<<<(nq + 255) / 256, 256>>>(qh, N_HEADS, D_MODEL);
        int nk = T_SEQ * N_KV * 32;
        rope_kernel_h<<<(nk + 255) / 256, 256>>>(kh, N_KV, KV_DIM);
    }

    // ---- attention (writes fp16 y)
    cudaFuncSetAttribute(attn_kernel, cudaFuncAttributeMaxDynamicSharedMemorySize, ATTN_SMEM_BYTES);
    attn_kernel<<<dim3(T_SEQ / 128, N_HEADS), 256, ATTN_SMEM_BYTES>>>(qh, kh, vh, yh);

    // ---- output projection (fp16 in, fp32 out)
    hgemm_out<<<dim3(D_MODEL / 128, T_SEQ / 128), 256>>>(yh, wot, out);
}

// round 17
// speedup vs baseline: 1.2096x; 1.0334x over previous
#include <cuda_runtime.h>
#include <cuda_fp16.h>
#include <math.h>
#include <cstdint>

// Problem constants
#define T_SEQ 4096
#define D_MODEL 2048
#define N_HEADS 16
#define N_KV 4
#define DH 128
#define HALF 64
#define KV_DIM 512   // N_KV * DH
#define QKV_N (D_MODEL + 2 * KV_DIM)   // 3072

// Scratch (device globals; no allocation allowed)
__device__ __half g_xh[T_SEQ * D_MODEL];          // x as fp16
__device__ __half g_wqkvt[QKV_N * D_MODEL];       // [Wq;Wk;Wv]^T as fp16 [n][k]
__device__ __half g_wot[D_MODEL * D_MODEL];       // Wo^T as fp16 [n][k]
__device__ float2 g_ropetab[T_SEQ * HALF];        // (sin, cos) per (t, i)
__device__ __half g_qh[T_SEQ * D_MODEL];
__device__ __half g_kh[T_SEQ * KV_DIM];
__device__ __half g_vh[T_SEQ * KV_DIM];
__device__ __half g_yh[T_SEQ * D_MODEL];          // attention output, fp16

// ---------------------------------------------------------------------------
// helpers
// ---------------------------------------------------------------------------
__device__ __forceinline__ uint32_t pack2h(float lo, float hi) {
    __half2 h = __floats2half2_rn(lo, hi);   // .x = lo -> low 16 bits
    return *(uint32_t*)&h;
}

__device__ __forceinline__ void mma_f16(float* d, const uint32_t* a,
                                        const uint32_t* b, const float* c) {
    asm volatile(
        "mma.sync.aligned.m16n8k16.row.col.f32.f16.f16.f32 "
        "{%0,%1,%2,%3}, {%4,%5,%6,%7}, {%8,%9}, {%10,%11,%12,%13};"
        : "=f"(d[0]), "=f"(d[1]), "=f"(d[2]), "=f"(d[3])
        : "r"(a[0]), "r"(a[1]), "r"(a[2]), "r"(a[3]),
          "r"(b[0]), "r"(b[1]),
          "f"(c[0]), "f"(c[1]), "f"(c[2]), "f"(c[3]));
}

__device__ __forceinline__ uint32_t smem_u32(const void* p) {
    uint32_t a;
    asm("{ .reg .u64 t; cvta.to.shared.u64 t, %1; cvt.u32.u64 %0, t; }" : "=r"(a) : "l"(p));
    return a;
}

__device__ __forceinline__ void ldmx4t(uint32_t& b0, uint32_t& b1,
                                       uint32_t& b2, uint32_t& b3, uint32_t addr) {
    asm volatile("ldmatrix.sync.aligned.m8n8.x4.trans.shared.b16 {%0,%1,%2,%3}, [%4];"
                 : "=r"(b0), "=r"(b1), "=r"(b2), "=r"(b3) : "r"(addr));
}

__device__ __forceinline__ void cpa16(uint32_t dst, const void* src) {
    asm volatile("cp.async.cg.shared.global [%0], [%1], 16;" :: "r"(dst), "l"(src));
}
__device__ __forceinline__ void cpa_commit() {
    asm volatile("cp.async.commit_group;" ::: "memory");
}
template <int N>
__device__ __forceinline__ void cpa_wait() {
    asm volatile("cp.async.wait_group %0;" :: "n"(N) : "memory");
}

// ---------------------------------------------------------------------------
// One-time operand preparation
// ---------------------------------------------------------------------------
__global__ void cvt_f32_f16(const float* __restrict__ in, __half* __restrict__ out) {
    int i = (blockIdx.x * blockDim.x + threadIdx.x) * 8;
    float4 a = *(const float4*)(in + i);
    float4 b = *(const float4*)(in + i + 4);
    uint4 u;
    u.x = pack2h(a.x, a.y); u.y = pack2h(a.z, a.w);
    u.z = pack2h(b.x, b.y); u.w = pack2h(b.z, b.w);
    *(uint4*)(out + i) = u;
}

// RoPE sin/cos table: tab[t*64 + i] = (sin(t*inv_i), cos(t*inv_i)),
// inv_i = 10000^(-i/64). Same fp32 expressions as the old rope kernel.
__global__ void rope_table(float2* __restrict__ tab) {
    int idx = blockIdx.x * blockDim.x + threadIdx.x;
    int i = idx & (HALF - 1);
    int t = idx >> 6;
    float inv = powf(10000.f, -(float)i / (float)HALF);
    float s, c;
    sincosf((float)t * inv, &s, &c);
    tab[idx] = make_float2(s, c);
}

// W[K][N] fp32 -> Wt[N][K] fp16, 64x64 tiles, block (32, 8)
__global__ void transpose_f32_f16(const float* __restrict__ W,
                                  __half* __restrict__ Wt, int K, int N) {
    __shared__ float tile[64][65];
    const int k0 = blockIdx.y * 64;
    const int n0 = blockIdx.x * 64;
    const int tx = threadIdx.x;
    const int ty = threadIdx.y;
#pragma unroll
    for (int l = 0; l < 8; ++l) {
        int r = ty + l * 8;
        tile[r][tx]      = W[(size_t)(k0 + r) * N + n0 + tx];
        tile[r][tx + 32] = W[(size_t)(k0 + r) * N + n0 + tx + 32];
    }
    __syncthreads();
#pragma unroll
    for (int l = 0; l < 8; ++l) {
        int n = ty + l * 8;
        uint32_t o = pack2h(tile[2 * tx][n], tile[2 * tx + 1][n]);
        *(uint32_t*)(Wt + (size_t)(n0 + n) * K + k0 + 2 * tx) = o;
    }
}

// ---------------------------------------------------------------------------
// FP16 GEMM with pure-copy staging; optional fused RoPE epilogue.
// A[M][K] fp16 row-major, Bt[N][K] fp16 k-major. CTA 128x128, BK=16, 256 thr.
// ---------------------------------------------------------------------------
struct SmemH {
    union {
        struct {
            uint32_t As[2][128][12];   // [buf][m][k2]
            uint32_t Bs[2][128][12];   // [buf][n][k2]
        } g;
        __half rope[128][132];          // rope exchange tile
    };
};

template <typename TOut, bool ROPE>
__device__ __forceinline__ void hgemm_body(
    SmemH& sm, const __half* __restrict__ A, const __half* __restrict__ Bt,
    TOut* __restrict__ C, const float2* __restrict__ tab,
    int K, int NC, int m0, int nb0, int cn0) {

    const int tid = threadIdx.x;
    const int wid = tid >> 5;
    const int lane = tid & 31;
    const int g = lane >> 2;
    const int t = lane & 3;
    const int wm = (wid & 3) * 32;
    const int wn = (wid >> 2) * 64;

    const int sRow = tid >> 1;
    const int sCh  = (tid & 1) * 4;

    float acc[2][8][4];
#pragma unroll
    for (int mt = 0; mt < 2; ++mt)
#pragma unroll
        for (int nt = 0; nt < 8; ++nt)
#pragma unroll
            for (int r = 0; r < 4; ++r) acc[mt][nt][r] = 0.f;

    uint4 av = *(const uint4*)(A + (size_t)(m0 + sRow) * K + sCh * 2);
    uint4 bv = *(const uint4*)(Bt + (size_t)(nb0 + sRow) * K + sCh * 2);
    *(uint4*)(&sm.g.As[0][sRow][sCh]) = av;
    *(uint4*)(&sm.g.Bs[0][sRow][sCh]) = bv;
    __syncthreads();

    const int KT = K >> 4;
    for (int kt = 0; kt < KT; ++kt) {
        const int buf = kt & 1;

        if (kt + 1 < KT) {
            const int k0n = (kt + 1) << 4;
            av = *(const uint4*)(A + (size_t)(m0 + sRow) * K + k0n + sCh * 2);
            bv = *(const uint4*)(Bt + (size_t)(nb0 + sRow) * K + k0n + sCh * 2);
        }

        uint32_t af[2][4];
#pragma unroll
        for (int mt = 0; mt < 2; ++mt) {
            const int r0 = wm + mt * 16;
            af[mt][0] = sm.g.As[buf][r0 + g][t];
            af[mt][1] = sm.g.As[buf][r0 + g + 8][t];
            af[mt][2] = sm.g.As[buf][r0 + g][4 + t];
            af[mt][3] = sm.g.As[buf][r0 + g + 8][4 + t];
        }
#pragma unroll
        for (int nt = 0; nt < 8; ++nt) {
            const int n = wn + nt * 8 + g;
            uint32_t bf[2] = {sm.g.Bs[buf][n][t], sm.g.Bs[buf][n][4 + t]};
#pragma unroll
            for (int mt = 0; mt < 2; ++mt)
                mma_f16(acc[mt][nt], af[mt], bf, acc[mt][nt]);
        }

        if (kt + 1 < KT) {
            const int nb = buf ^ 1;
            *(uint4*)(&sm.g.As[nb][sRow][sCh]) = av;
            *(uint4*)(&sm.g.Bs[nb][sRow][sCh]) = bv;
            __syncthreads();
        }
    }

    if (ROPE) {
        // fp16-round acc into the exchange tile (same rounding point as the
        // old gemm-store), then rope pairs (i, i+64) in fp32, store fp16.
        __syncthreads();   // all mainloop smem reads done before overwrite
#pragma unroll
        for (int mt = 0; mt < 2; ++mt) {
            const int r = wm + mt * 16 + g;
#pragma unroll
            for (int nt = 0; nt < 8; ++nt) {
                const int c = wn + nt * 8 + t * 2;
                *(uint32_t*)&sm.rope[r][c]     = pack2h(acc[mt][nt][0], acc[mt][nt][1]);
                *(uint32_t*)&sm.rope[r + 8][c] = pack2h(acc[mt][nt][2], acc[mt][nt][3]);
            }
        }
        __syncthreads();

        // 128 rows x 32 items (each item: 2 cols of first half + 2 of second)
        // = 4096 items = 16 per thread.  (R16 bug: this loop ran only 8x.)
        __half* Ch = (__half*)C;
#pragma unroll
        for (int l = 0; l < 16; ++l) {
            int idx = tid + l * 256;
            int row = idx >> 5;                 // 0..127
            int i0 = (idx & 31) * 2;            // 0..62
            float2 sc0 = tab[(size_t)(m0 + row) * HALF + i0];
            float2 sc1 = tab[(size_t)(m0 + row) * HALF + i0 + 1];
            float2 a = __half22float2(*(__half2*)&sm.rope[row][i0]);
            float2 b = __half22float2(*(__half2*)&sm.rope[row][i0 + 64]);
            uint32_t o1 = pack2h(a.x * sc0.y - b.x * sc0.x,
                                 a.y * sc1.y - b.y * sc1.x);
            uint32_t o2 = pack2h(a.x * sc0.x + b.x * sc0.y,
                                 a.y * sc1.x + b.y * sc1.y);
            __half* base = Ch + (size_t)(m0 + row) * NC + cn0;
            *(uint32_t*)(base + i0)      = o1;
            *(uint32_t*)(base + i0 + 64) = o2;
        }
    } else {
#pragma unroll
        for (int mt = 0; mt < 2; ++mt) {
            const int r0 = m0 + wm + mt * 16;
#pragma unroll
            for (int nt = 0; nt < 8; ++nt) {
                const int c0 = cn0 + wn + nt * 8 + t * 2;
                if (sizeof(TOut) == 4) {
                    float* Cf = (float*)C;
                    *(float2*)(Cf + (size_t)(r0 + g) * NC + c0) =
                        make_float2(acc[mt][nt][0], acc[mt][nt][1]);
                    *(float2*)(Cf + (size_t)(r0 + g + 8) * NC + c0) =
                        make_float2(acc[mt][nt][2], acc[mt][nt][3]);
                } else {
                    __half* Ch = (__half*)C;
                    *(uint32_t*)(Ch + (size_t)(r0 + g) * NC + c0) =
                        pack2h(acc[mt][nt][0], acc[mt][nt][1]);
                    *(uint32_t*)(Ch + (size_t)(r0 + g + 8) * NC + c0) =
                        pack2h(acc[mt][nt][2], acc[mt][nt][3]);
                }
            }
        }
    }
}

// Fused Q/K/V projection + RoPE (q, k tiles rope; v tiles plain).
__global__ __launch_bounds__(256, 2)
void hgemm_qkv(const __half* __restrict__ xh, const __half* __restrict__ Wqkvt,
               const float2* __restrict__ tab,
               __half* __restrict__ q, __half* __restrict__ k,
               __half* __restrict__ v) {
    __shared__ SmemH sm;
    const int n0c = blockIdx.x * 128;
    const int m0 = blockIdx.y * 128;
    if (n0c < D_MODEL) {
        hgemm_body<__half, true>(sm, xh, Wqkvt, q, tab, D_MODEL, D_MODEL, m0, n0c, n0c);
    } else if (n0c < D_MODEL + KV_DIM) {
        hgemm_body<__half, true>(sm, xh, Wqkvt, k, tab, D_MODEL, KV_DIM, m0, n0c,
                                 n0c - D_MODEL);
    } else {
        hgemm_body<__half, false>(sm, xh, Wqkvt, v, tab, D_MODEL, KV_DIM, m0, n0c,
                                  n0c - D_MODEL - KV_DIM);
    }
}

// Output projection: A = yh fp16, Bt = Wot fp16, C = out fp32.
__global__ __launch_bounds__(256, 2)
void hgemm_out(const __half* __restrict__ yh, const __half* __restrict__ Wot,
               float* __restrict__ out) {
    __shared__ SmemH sm;
    hgemm_body<float, false>(sm, yh, Wot, out, nullptr, D_MODEL, D_MODEL,
                             blockIdx.y * 128, blockIdx.x * 128, blockIdx.x * 128);
}

// ---------------------------------------------------------------------------
// Flash attention v7 (unchanged): 256 threads / 8 warps over 128 q rows;
// cp.async double-buffered K/V; writes y as fp16.
// ---------------------------------------------------------------------------
#define AOQ  0
#define AOK0 8704
#define AOK1 13056
#define AOV0 17408
#define AOV1 21760
#define ATTN_SMEM_BYTES (26112 * 4)   // 104448

__global__ __launch_bounds__(256, 2)
void attn_kernel(const __half* __restrict__ q, const __half* __restrict__ k,
                 const __half* __restrict__ v, __half* __restrict__ y) {
    extern __shared__ uint32_t smu[];
    uint32_t* Qh = smu + AOQ;

    const int qb = (gridDim.x - 1) - blockIdx.x;   // heavy blocks first
    const int hq = blockIdx.y;
    const int hkv = hq >> 2;
    const int q0 = qb * 128;
    const int tid = threadIdx.x;
    const int wid = tid >> 5;
    const int lane = tid & 31;
    const int g = lane >> 2;
    const int t = lane & 3;
    const int r0 = wid * 16;
    const int rg0 = q0 + r0 + g;
    const int rg1 = rg0 + 8;

    const int sRow = tid >> 4;
    const int sD16 = tid & 15;

    const uint32_t kBase[2] = {smem_u32(smu + AOK0), smem_u32(smu + AOK1)};
    const uint32_t vBase[2] = {smem_u32(smu + AOV0), smem_u32(smu + AOV1)};

    // stage Q once
#pragma unroll
    for (int l = 0; l < 8; ++l) {
        int lin = tid + l * 256;
        int row = lin >> 4;
        int d8 = lin & 15;
        uint4 u = *(const uint4*)(q + (size_t)(q0 + row) * D_MODEL + hq * DH + d8 * 8);
        *(uint4*)(Qh + row * 68 + d8 * 4) = u;
    }

    // async K/V block 0 -> buffer 0
    {
        const __half* kp = k + hkv * DH;
        const __half* vp = v + hkv * DH;
#pragma unroll
        for (int l = 0; l < 4; ++l) {
            int row = sRow + l * 16;
            cpa16(kBase[0] + row * 272 + sD16 * 16, kp + (size_t)row * KV_DIM + sD16 * 8);
            cpa16(vBase[0] + row * 272 + sD16 * 16, vp + (size_t)row * KV_DIM + sD16 * 8);
        }
        cpa_commit();
    }

    float acc[16][4];
#pragma unroll
    for (int n = 0; n < 16; ++n)
#pragma unroll
        for (int r = 0; r < 4; ++r) acc[n][r] = 0.f;
    float m_i[2] = {-1e30f, -1e30f};
    float l_i[2] = {0.f, 0.f};

    const float scale = 0.08838834764831845f;   // 1/sqrt(128)

    const int nkb = 2 * qb + 2;
    for (int jb = 0; jb < nkb; ++jb) {
        const int j0 = jb * 64;
        const int buf = jb & 1;
        __syncthreads();

        if (jb + 1 < nkb) {
            const int jn = (jb + 1) * 64;
            const int nb = buf ^ 1;
            const __half* kp = k + (size_t)jn * KV_DIM + hkv * DH;
            const __half* vp = v + (size_t)jn * KV_DIM + hkv * DH;
#pragma unroll
            for (int l = 0; l < 4; ++l) {
                int row = sRow + l * 16;
                cpa16(kBase[nb] + row * 272 + sD16 * 16, kp + (size_t)row * KV_DIM + sD16 * 8);
                cpa16(vBase[nb] + row * 272 + sD16 * 16, vp + (size_t)row * KV_DIM + sD16 * 8);
            }
            cpa_commit();
            cpa_wait<1>();
        } else {
            cpa_wait<0>();
        }
        __syncthreads();

        if (j0 > q0 + r0 + 15) continue;

        const uint32_t* Kh = smu + (buf ? AOK1 : AOK0);
        const __half*   Vh = (const __half*)(smu + (buf ? AOV1 : AOV0));

        // S = Q K^T
        float sf[8][4];
#pragma unroll
        for (int nt = 0; nt < 8; ++nt)
#pragma unroll
            for (int r = 0; r < 4; ++r) sf[nt][r] = 0.f;

        const uint32_t* qr0 = Qh + (r0 + g) * 68;
        const uint32_t* qr1 = Qh + (r0 + g + 8) * 68;
#pragma unroll
        for (int ks = 0; ks < 8; ++ks) {
            const int kk = ks * 8;
            uint32_t a[4] = {qr0[kk + t], qr1[kk + t], qr0[kk + 4 + t], qr1[kk + 4 + t]};
#pragma unroll
            for (int nt = 0; nt < 8; ++nt) {
                const uint32_t* kr = Kh + (nt * 8 + g) * 68 + kk;
                uint32_t b[2] = {kr[t], kr[4 + t]};
                mma_f16(sf[nt], a, b, sf[nt]);
            }
        }

        // scale + causal mask
#pragma unroll
        for (int nt = 0; nt < 8; ++nt) {
            sf[nt][0] *= scale; sf[nt][1] *= scale;
            sf[nt][2] *= scale; sf[nt][3] *= scale;
        }
        if (j0 + 63 > rg0) {
#pragma unroll
            for (int nt = 0; nt < 8; ++nt) {
                const int c = j0 + nt * 8 + 2 * t;
                if (c     > rg0) sf[nt][0] = -1e30f;
                if (c + 1 > rg0) sf[nt][1] = -1e30f;
                if (c     > rg1) sf[nt][2] = -1e30f;
                if (c + 1 > rg1) sf[nt][3] = -1e30f;
            }
        }

        // online softmax (quad-local)
        float mx0 = -1e30f, mx1 = -1e30f;
#pragma unroll
        for (int nt = 0; nt < 8; ++nt) {
            mx0 = fmaxf(mx0, fmaxf(sf[nt][0], sf[nt][1]));
            mx1 = fmaxf(mx1, fmaxf(sf[nt][2], sf[nt][3]));
        }
        mx0 = fmaxf(mx0, __shfl_xor_sync(0xffffffffu, mx0, 1));
        mx0 = fmaxf(mx0, __shfl_xor_sync(0xffffffffu, mx0, 2));
        mx1 = fmaxf(mx1, __shfl_xor_sync(0xffffffffu, mx1, 1));
        mx1 = fmaxf(mx1, __shfl_xor_sync(0xffffffffu, mx1, 2));

        const float mn0 = fmaxf(m_i[0], mx0);
        const float mn1 = fmaxf(m_i[1], mx1);
        const float al0 = __expf(m_i[0] - mn0);
        const float al1 = __expf(m_i[1] - mn1);

        float sum0 = 0.f, sum1 = 0.f;
#pragma unroll
        for (int nt = 0; nt < 8; ++nt) {
            sf[nt][0] = __expf(sf[nt][0] - mn0);
            sf[nt][1] = __expf(sf[nt][1] - mn0);
            sf[nt][2] = __expf(sf[nt][2] - mn1);
            sf[nt][3] = __expf(sf[nt][3] - mn1);
            sum0 += sf[nt][0] + sf[nt][1];
            sum1 += sf[nt][2] + sf[nt][3];
        }
        sum0 += __shfl_xor_sync(0xffffffffu, sum0, 1);
        sum0 += __shfl_xor_sync(0xffffffffu, sum0, 2);
        sum1 += __shfl_xor_sync(0xffffffffu, sum1, 1);
        sum1 += __shfl_xor_sync(0xffffffffu, sum1, 2);

        l_i[0] = l_i[0] * al0 + sum0;
        l_i[1] = l_i[1] * al1 + sum1;
        m_i[0] = mn0;
        m_i[1] = mn1;

#pragma unroll
        for (int n = 0; n < 16; ++n) {
            acc[n][0] *= al0; acc[n][1] *= al0;
            acc[n][2] *= al1; acc[n][3] *= al1;
        }

        // O += P V
        const int vrow = lane & 15;
        const int vcol8 = (lane >> 4) * 8;
#pragma unroll
        for (int ks = 0; ks < 4; ++ks) {
            uint32_t a[4] = {pack2h(sf[2 * ks][0],     sf[2 * ks][1]),
                             pack2h(sf[2 * ks][2],     sf[2 * ks][3]),
                             pack2h(sf[2 * ks + 1][0], sf[2 * ks + 1][1]),
                             pack2h(sf[2 * ks + 1][2], sf[2 * ks + 1][3])};
            const __half* vbase = Vh + (16 * ks + vrow) * 136 + vcol8;
#pragma unroll
            for (int ntp = 0; ntp < 8; ++ntp) {
                uint32_t b0, b1, b2, b3;
                ldmx4t(b0, b1, b2, b3, smem_u32(vbase + ntp * 16));
                uint32_t blo[2] = {b0, b1};
                uint32_t bhi[2] = {b2, b3};
                mma_f16(acc[2 * ntp],     a, blo, acc[2 * ntp]);
                mma_f16(acc[2 * ntp + 1], a, bhi, acc[2 * ntp + 1]);
            }
        }
    }

    // normalize + write y as fp16
    const float i0 = 1.f / l_i[0];
    const float i1 = 1.f / l_i[1];
    __half* y0 = y + (size_t)rg0 * D_MODEL + hq * DH;
    __half* y1 = y + (size_t)rg1 * D_MODEL + hq * DH;
#pragma unroll
    for (int n = 0; n < 16; ++n) {
        const int c0 = n * 8 + 2 * t;
        *(uint32_t*)(y0 + c0) = pack2h(acc[n][0] * i0, acc[n][1] * i0);
        *(uint32_t*)(y1 + c0) = pack2h(acc[n][2] * i1, acc[n][3] * i1);
    }
}

// ---------------------------------------------------------------------------
extern "C" void kernel_launch(void* const* d_in, const int* in_sizes, int n_in,
                              void* d_out, int out_size) {
    const float* x  = (const float*)d_in[0];
    const float* Wq = (const float*)d_in[1];
    const float* Wk = (const float*)d_in[2];
    const float* Wv = (const float*)d_in[3];
    const float* Wo = (const float*)d_in[4];
    float* out = (float*)d_out;

    void *pxh, *pwqkvt, *pwot, *ptab, *pq, *pk, *pv, *py;
    cudaGetSymbolAddress(&pxh, g_xh);
    cudaGetSymbolAddress(&pwqkvt, g_wqkvt);
    cudaGetSymbolAddress(&pwot, g_wot);
    cudaGetSymbolAddress(&ptab, g_ropetab);
    cudaGetSymbolAddress(&pq, g_qh);
    cudaGetSymbolAddress(&pk, g_kh);
    cudaGetSymbolAddress(&pv, g_vh);
    cudaGetSymbolAddress(&py, g_yh);
    __half* xh    = (__half*)pxh;
    __half* wqkvt = (__half*)pwqkvt;
    __half* wot   = (__half*)pwot;
    float2* tab   = (float2*)ptab;
    __half* qh    = (__half*)pq;
    __half* kh    = (__half*)pk;
    __half* vh    = (__half*)pv;
    __half* yh    = (__half*)py;

    // ---- operand prep
    cvt_f32_f16<<<(T_SEQ * D_MODEL) / (256 * 8), 256>>>(x, xh);
    rope_table<<<(T_SEQ * HALF) / 256, 256>>>(tab);
    {
        dim3 thr(32, 8);
        transpose_f32_f16<<<dim3(D_MODEL / 64, D_MODEL / 64), thr>>>(Wq, wqkvt, D_MODEL, D_MODEL);
        transpose_f32_f16<<<dim3(KV_DIM / 64, D_MODEL / 64), thr>>>(
            Wk, wqkvt + (size_t)D_MODEL * D_MODEL, D_MODEL, KV_DIM);
        transpose_f32_f16<<<dim3(KV_DIM / 64, D_MODEL / 64), thr>>>(
            Wv, wqkvt + (size_t)(D_MODEL + KV_DIM) * D_MODEL, D_MODEL, KV_DIM);
        transpose_f32_f16<<<dim3(D_MODEL / 64, D_MODEL / 64), thr>>>(Wo, wot, D_MODEL, D_MODEL);
    }

    // ---- fused Q/K/V projection + RoPE
    hgemm_qkv<<<dim3(QKV_N / 128, T_SEQ / 128), 256>>>(xh, wqkvt, tab, qh, kh, vh);

    // ---- attention (writes fp16 y)
    cudaFuncSetAttribute(attn_kernel, cudaFuncAttributeMaxDynamicSharedMemorySize, ATTN_SMEM_BYTES);
    attn_kernel<<<dim3(T_SEQ / 128, N_HEADS), 256, ATTN_SMEM_BYTES>>>(qh, kh, vh, yh);

    // ---- output projection (fp16 in, fp32 out)
    hgemm_out<<<dim3(D_MODEL / 128, T_SEQ / 128), 256>>>(yh, wot, out);
}